// round 1
// baseline (speedup 1.0000x reference)
#include <cuda_runtime.h>

// ---------------- problem constants ----------------
constexpr int N_INTn = 50000;
constexpr int D      = 128;
constexpr int DCn    = 64;
constexpr int DMn    = 128;
constexpr int DHn    = 256;
constexpr int E_INTn = 500000;
constexpr int E_Bn   = 20000;
constexpr int E_Cn   = 10000;

constexpr int TM   = 64;    // rows per CTA tile
constexpr int NT   = 512;   // threads per CTA
constexpr int SWLD = 132;   // padded lda for staged weight tile [32][128]

// ---------------- scratch (device globals; no allocation allowed) ----------------
__device__ float g_aggS[N_INTn * D];     // sum of x[src] per target (interior edges)
__device__ float g_aggB[N_INTn * D];     // sum of x_bound[e] per target
__device__ float g_aggC[N_INTn * DCn];   // sum of u[e] per target
__device__ float g_cntI[N_INTn];
__device__ float g_cntB[N_INTn];
__device__ float g_cntC[N_INTn];

// ---------------- helpers ----------------
__device__ __forceinline__ void red4(float* p, float4 v) {
    asm volatile("red.global.add.v4.f32 [%0], {%1,%2,%3,%4};"
                 :: "l"(p), "f"(v.x), "f"(v.y), "f"(v.z), "f"(v.w) : "memory");
}

#define FMA8(t, xv, wa, wb)                                        \
    t[0] = fmaf(xv, wa.x, t[0]); t[1] = fmaf(xv, wa.y, t[1]);      \
    t[2] = fmaf(xv, wa.z, t[2]); t[3] = fmaf(xv, wa.w, t[3]);      \
    t[4] = fmaf(xv, wb.x, t[4]); t[5] = fmaf(xv, wb.y, t[5]);      \
    t[6] = fmaf(xv, wb.z, t[6]); t[7] = fmaf(xv, wb.w, t[7]);

// Cooperative (all NT threads) tile-GEMM accumulate:
//   t0/t1 (+)= sX[n0 / n0+1][kofs..kofs+K] dot W[j][kofs..kofs+K]  for j = j0..j0+7
// W is row-major [128 rows within this call][ldw]; if kofs2 >= 0 the two column
// blocks kofs and kofs2 are summed at staging time (for the concat([a,a]) weights).
__device__ __forceinline__ void pair_mm(
    float t0[8], float t1[8],
    const float* sX, int ldx, int n0,
    const float* __restrict__ Wg, int ldw, int kofs, int kofs2, int K,
    float* sW, int j0, int tid)
{
    for (int kc = 0; kc < K; kc += 32) {
        __syncthreads();
        {
            int k  = tid & 31;
            int jb = tid >> 5;            // 0..15
            #pragma unroll
            for (int rep = 0; rep < 8; rep++) {
                int j = jb + rep * 16;
                float w = Wg[j * ldw + kofs + kc + k];
                if (kofs2 >= 0) w += Wg[j * ldw + kofs2 + kc + k];
                sW[k * SWLD + j] = w;
            }
        }
        __syncthreads();
        const float* xr0 = sX + n0 * ldx + kc;
        const float* xr1 = xr0 + ldx;
        #pragma unroll
        for (int k2 = 0; k2 < 32; k2++) {
            float x0 = xr0[k2];
            float x1 = xr1[k2];
            const float4* wp = reinterpret_cast<const float4*>(sW + k2 * SWLD + j0);
            float4 wa = wp[0];
            float4 wb = wp[1];
            FMA8(t0, x0, wa, wb)
            FMA8(t1, x1, wa, wb)
        }
    }
}

// ---------------- zero scratch ----------------
__global__ void k_zero() {
    int idx = blockIdx.x * blockDim.x + threadIdx.x;
    int stride = gridDim.x * blockDim.x;
    float4 z = {0.f, 0.f, 0.f, 0.f};
    float4* a = reinterpret_cast<float4*>(g_aggS);
    float4* b = reinterpret_cast<float4*>(g_aggB);
    float4* c = reinterpret_cast<float4*>(g_aggC);
    for (int i = idx; i < N_INTn * D / 4; i += stride) { a[i] = z; b[i] = z; }
    for (int i = idx; i < N_INTn * DCn / 4; i += stride) c[i] = z;
    for (int i = idx; i < N_INTn; i += stride) {
        g_cntI[i] = 0.f; g_cntB[i] = 0.f; g_cntC[i] = 0.f;
    }
}

// ---------------- edge feature scatter (one warp per edge) ----------------
__global__ void k_scatter_int(const int* __restrict__ ei, const float* __restrict__ x) {
    int w = (blockIdx.x * blockDim.x + threadIdx.x) >> 5;
    int lane = threadIdx.x & 31;
    if (w >= E_INTn) return;
    int s = ei[w];
    int t = ei[E_INTn + w];
    float4 v = reinterpret_cast<const float4*>(x + (size_t)s * D)[lane];
    red4(g_aggS + (size_t)t * D + lane * 4, v);
    if (lane == 0) atomicAdd(&g_cntI[t], 1.0f);
}

__global__ void k_scatter_b(const int* __restrict__ ei, const float* __restrict__ xb) {
    int w = (blockIdx.x * blockDim.x + threadIdx.x) >> 5;
    int lane = threadIdx.x & 31;
    if (w >= E_Bn) return;
    int t = ei[E_Bn + w];
    float4 v = reinterpret_cast<const float4*>(xb + (size_t)w * D)[lane];
    red4(g_aggB + (size_t)t * D + lane * 4, v);
    if (lane == 0) atomicAdd(&g_cntB[t], 1.0f);
}

__global__ void k_scatter_c(const int* __restrict__ ei, const float* __restrict__ u) {
    int w = (blockIdx.x * blockDim.x + threadIdx.x) >> 5;
    int lane = threadIdx.x & 31;
    if (w >= E_Cn) return;
    int t = ei[E_Cn + w];
    if (lane < 16) {
        float4 v = reinterpret_cast<const float4*>(u + (size_t)w * DCn)[lane];
        red4(g_aggC + (size_t)t * DCn + lane * 4, v);
    }
    if (lane == 0) atomicAdd(&g_cntC[t], 1.0f);
}

// ---------------- interior node update ----------------
struct SmemInt {
    float x[TM * D];
    float aS[TM * D];
    float aB[TM * D];
    float aC[TM * DCn];
    float agg[TM * D];
    float w[32 * SWLD];
    float bii[DMn], bbi[DMn], bci[DMn];
    float bis[DHn], bim[DHn];
    float cI[TM], cB[TM], cC[TM];
};

__global__ void __launch_bounds__(NT) k_interior(
    const float* __restrict__ x,
    const float* __restrict__ Wii, const float* __restrict__ bii,
    const float* __restrict__ Wbi, const float* __restrict__ bbi,
    const float* __restrict__ Wci, const float* __restrict__ bci,
    const float* __restrict__ Wim, const float* __restrict__ bim,
    const float* __restrict__ Wis, const float* __restrict__ bis,
    float* __restrict__ out)
{
    extern __shared__ float sm[];
    SmemInt& S = *reinterpret_cast<SmemInt*>(sm);
    int tid = threadIdx.x;
    int nbase = blockIdx.x * TM;
    const float4 z4 = {0.f, 0.f, 0.f, 0.f};

    // stage node tiles
    for (int i = tid; i < TM * D / 4; i += NT) {
        int r = i / (D / 4), c = i % (D / 4);
        int n = nbase + r;
        bool ok = n < N_INTn;
        reinterpret_cast<float4*>(S.x)[i]  = ok ? reinterpret_cast<const float4*>(x      + (size_t)n * D)[c] : z4;
        reinterpret_cast<float4*>(S.aS)[i] = ok ? reinterpret_cast<const float4*>(g_aggS + (size_t)n * D)[c] : z4;
        reinterpret_cast<float4*>(S.aB)[i] = ok ? reinterpret_cast<const float4*>(g_aggB + (size_t)n * D)[c] : z4;
    }
    for (int i = tid; i < TM * DCn / 4; i += NT) {
        int r = i / (DCn / 4), c = i % (DCn / 4);
        int n = nbase + r;
        reinterpret_cast<float4*>(S.aC)[i] = (n < N_INTn) ? reinterpret_cast<const float4*>(g_aggC + (size_t)n * DCn)[c] : z4;
    }
    if (tid < TM) {
        int n = nbase + tid;
        bool ok = n < N_INTn;
        S.cI[tid] = ok ? g_cntI[n] : 0.f;
        S.cB[tid] = ok ? g_cntB[n] : 0.f;
        S.cC[tid] = ok ? g_cntC[n] : 0.f;
    }
    if (tid < DMn) { S.bii[tid] = bii[tid]; S.bbi[tid] = bbi[tid]; S.bci[tid] = bci[tid]; }
    if (tid < DHn) { S.bis[tid] = bis[tid]; S.bim[tid] = bim[tid]; }
    // (pair_mm begins with __syncthreads — staged data is visible)

    int tx = tid & 15, ty = tid >> 4;
    int j0 = tx * 8, n0l = ty * 2;

    // ---- phase 1: aggregated message sum -> agg ----
    float acc0[8], acc1[8];
    #pragma unroll
    for (int i = 0; i < 8; i++) { acc0[i] = 0.f; acc1[i] = 0.f; }

    float ci0, ci1, cb0, cb1, cc0, cc1;

    {
        float t0[8], t1[8];
        // (AggS) @ Wii[:, :128].T
        #pragma unroll
        for (int i = 0; i < 8; i++) { t0[i] = 0.f; t1[i] = 0.f; }
        pair_mm(t0, t1, S.aS, D, n0l, Wii, 2 * D, 0, -1, 128, S.w, j0, tid);
        ci0 = S.cI[n0l]; ci1 = S.cI[n0l + 1];
        cb0 = S.cB[n0l]; cb1 = S.cB[n0l + 1];
        cc0 = S.cC[n0l]; cc1 = S.cC[n0l + 1];
        #pragma unroll
        for (int i = 0; i < 8; i++) { acc0[i] += t0[i]; acc1[i] += t1[i]; }

        // ci * x @ Wii[:, 128:].T
        #pragma unroll
        for (int i = 0; i < 8; i++) { t0[i] = 0.f; t1[i] = 0.f; }
        pair_mm(t0, t1, S.x, D, n0l, Wii, 2 * D, 128, -1, 128, S.w, j0, tid);
        #pragma unroll
        for (int i = 0; i < 8; i++) { acc0[i] = fmaf(ci0, t0[i], acc0[i]); acc1[i] = fmaf(ci1, t1[i], acc1[i]); }

        // (AggB) @ Wbi[:, :128].T
        #pragma unroll
        for (int i = 0; i < 8; i++) { t0[i] = 0.f; t1[i] = 0.f; }
        pair_mm(t0, t1, S.aB, D, n0l, Wbi, 2 * D, 0, -1, 128, S.w, j0, tid);
        #pragma unroll
        for (int i = 0; i < 8; i++) { acc0[i] += t0[i]; acc1[i] += t1[i]; }

        // cb * x @ Wbi[:, 128:].T
        #pragma unroll
        for (int i = 0; i < 8; i++) { t0[i] = 0.f; t1[i] = 0.f; }
        pair_mm(t0, t1, S.x, D, n0l, Wbi, 2 * D, 128, -1, 128, S.w, j0, tid);
        #pragma unroll
        for (int i = 0; i < 8; i++) { acc0[i] = fmaf(cb0, t0[i], acc0[i]); acc1[i] = fmaf(cb1, t1[i], acc1[i]); }

        // (AggC) @ Wci[:, :64].T
        #pragma unroll
        for (int i = 0; i < 8; i++) { t0[i] = 0.f; t1[i] = 0.f; }
        pair_mm(t0, t1, S.aC, DCn, n0l, Wci, D + DCn, 0, -1, 64, S.w, j0, tid);
        #pragma unroll
        for (int i = 0; i < 8; i++) { acc0[i] += t0[i]; acc1[i] += t1[i]; }

        // cc * x @ Wci[:, 64:].T
        #pragma unroll
        for (int i = 0; i < 8; i++) { t0[i] = 0.f; t1[i] = 0.f; }
        pair_mm(t0, t1, S.x, D, n0l, Wci, D + DCn, 64, -1, 128, S.w, j0, tid);
        #pragma unroll
        for (int i = 0; i < 8; i++) { acc0[i] = fmaf(cc0, t0[i], acc0[i]); acc1[i] = fmaf(cc1, t1[i], acc1[i]); }
    }

    // divide by counts, add per-message biases, stash agg
    {
        float cnt0 = ci0 + cb0 + cc0;
        float cnt1 = ci1 + cb1 + cc1;
        float inv0 = 1.f / fmaxf(cnt0, 1.f);
        float inv1 = 1.f / fmaxf(cnt1, 1.f);
        #pragma unroll
        for (int i = 0; i < 8; i++) {
            int j = j0 + i;
            float bsum = 0.f;
            S.agg[n0l * D + j] =
                (acc0[i] + ci0 * S.bii[j] + cb0 * S.bbi[j] + cc0 * S.bci[j]) * inv0;
            S.agg[(n0l + 1) * D + j] =
                (acc1[i] + ci1 * S.bii[j] + cb1 * S.bbi[j] + cc1 * S.bci[j]) * inv1;
            (void)bsum;
        }
    }

    // ---- phase 2: out = x @ Wis.T + agg @ Wim.T + (bis + bim) ----
    int ng0 = nbase + n0l;
    int ng1 = ng0 + 1;
    for (int jh = 0; jh < 2; jh++) {
        float a0[8], a1[8];
        #pragma unroll
        for (int i = 0; i < 8; i++) { a0[i] = 0.f; a1[i] = 0.f; }
        pair_mm(a0, a1, S.x,   D, n0l, Wis + jh * 128 * D, D, 0, -1, 128, S.w, j0, tid);
        pair_mm(a0, a1, S.agg, D, n0l, Wim + jh * 128 * D, D, 0, -1, 128, S.w, j0, tid);

        int jo = jh * 128 + j0;
        if (ng0 < N_INTn) {
            float4 v0, v1;
            v0.x = a0[0] + S.bis[jo + 0] + S.bim[jo + 0];
            v0.y = a0[1] + S.bis[jo + 1] + S.bim[jo + 1];
            v0.z = a0[2] + S.bis[jo + 2] + S.bim[jo + 2];
            v0.w = a0[3] + S.bis[jo + 3] + S.bim[jo + 3];
            v1.x = a0[4] + S.bis[jo + 4] + S.bim[jo + 4];
            v1.y = a0[5] + S.bis[jo + 5] + S.bim[jo + 5];
            v1.z = a0[6] + S.bis[jo + 6] + S.bim[jo + 6];
            v1.w = a0[7] + S.bis[jo + 7] + S.bim[jo + 7];
            reinterpret_cast<float4*>(out + (size_t)ng0 * DHn + jo)[0] = v0;
            reinterpret_cast<float4*>(out + (size_t)ng0 * DHn + jo)[1] = v1;
        }
        if (ng1 < N_INTn) {
            float4 v0, v1;
            v0.x = a1[0] + S.bis[jo + 0] + S.bim[jo + 0];
            v0.y = a1[1] + S.bis[jo + 1] + S.bim[jo + 1];
            v0.z = a1[2] + S.bis[jo + 2] + S.bim[jo + 2];
            v0.w = a1[3] + S.bis[jo + 3] + S.bim[jo + 3];
            v1.x = a1[4] + S.bis[jo + 4] + S.bim[jo + 4];
            v1.y = a1[5] + S.bis[jo + 5] + S.bim[jo + 5];
            v1.z = a1[6] + S.bis[jo + 6] + S.bim[jo + 6];
            v1.w = a1[7] + S.bis[jo + 7] + S.bim[jo + 7];
            reinterpret_cast<float4*>(out + (size_t)ng1 * DHn + jo)[0] = v0;
            reinterpret_cast<float4*>(out + (size_t)ng1 * DHn + jo)[1] = v1;
        }
    }
}

// ---------------- boundary node update ----------------
struct SmemB {
    float x[TM * D];
    float sb[TM * D];
    float w[32 * SWLD];
    float bbb[DMn];
    float bbs[DHn];
    float bbm[DHn];
};

__global__ void __launch_bounds__(NT) k_boundary(
    const float* __restrict__ xb,
    const float* __restrict__ Wbb, const float* __restrict__ bbb,
    const float* __restrict__ Wbs, const float* __restrict__ bbs,
    const float* __restrict__ Wbm, const float* __restrict__ bbm,
    float* __restrict__ out)
{
    extern __shared__ float sm[];
    SmemB& S = *reinterpret_cast<SmemB*>(sm);
    int tid = threadIdx.x;
    int rbase = blockIdx.x * TM;
    const float4 z4 = {0.f, 0.f, 0.f, 0.f};

    for (int i = tid; i < TM * D / 4; i += NT) {
        int r = i / (D / 4), c = i % (D / 4);
        int g = rbase + r;
        reinterpret_cast<float4*>(S.x)[i] = (g < E_Bn) ? reinterpret_cast<const float4*>(xb + (size_t)g * D)[c] : z4;
    }
    if (tid < DMn) S.bbb[tid] = bbb[tid];
    if (tid < DHn) { S.bbs[tid] = bbs[tid]; S.bbm[tid] = bbm[tid]; }

    int tx = tid & 15, ty = tid >> 4;
    int j0 = tx * 8, n0l = ty * 2;

    // phase 1: sb = xb @ (Wbb[:,:128] + Wbb[:,128:]).T + bbb
    {
        float t0[8], t1[8];
        #pragma unroll
        for (int i = 0; i < 8; i++) { t0[i] = 0.f; t1[i] = 0.f; }
        pair_mm(t0, t1, S.x, D, n0l, Wbb, 2 * D, 0, D, 128, S.w, j0, tid);
        #pragma unroll
        for (int i = 0; i < 8; i++) {
            S.sb[n0l * D + j0 + i]       = t0[i] + S.bbb[j0 + i];
            S.sb[(n0l + 1) * D + j0 + i] = t1[i] + S.bbb[j0 + i];
        }
    }

    // phase 2
    int g0 = rbase + n0l, g1 = g0 + 1;
    for (int jh = 0; jh < 2; jh++) {
        float a0[8], a1[8];
        #pragma unroll
        for (int i = 0; i < 8; i++) { a0[i] = 0.f; a1[i] = 0.f; }
        pair_mm(a0, a1, S.x,  D, n0l, Wbs + jh * 128 * D, D, 0, -1, 128, S.w, j0, tid);
        pair_mm(a0, a1, S.sb, D, n0l, Wbm + jh * 128 * D, D, 0, -1, 128, S.w, j0, tid);
        int jo = jh * 128 + j0;
        if (g0 < E_Bn) {
            #pragma unroll
            for (int i = 0; i < 8; i++)
                out[(size_t)g0 * DHn + jo + i] = a0[i] + S.bbs[jo + i] + S.bbm[jo + i];
        }
        if (g1 < E_Bn) {
            #pragma unroll
            for (int i = 0; i < 8; i++)
                out[(size_t)g1 * DHn + jo + i] = a1[i] + S.bbs[jo + i] + S.bbm[jo + i];
        }
    }
}

// ---------------- control node update ----------------
struct SmemC {
    float u[TM * DCn];
    float sc[TM * D];
    float w[32 * SWLD];
    float bcc[DMn];
    float bcs[DHn];
    float bcm[DHn];
};

__global__ void __launch_bounds__(NT) k_control(
    const float* __restrict__ u,
    const float* __restrict__ Wcc, const float* __restrict__ bcc,
    const float* __restrict__ Wcs, const float* __restrict__ bcs,
    const float* __restrict__ Wcm, const float* __restrict__ bcm,
    float* __restrict__ out)
{
    extern __shared__ float sm[];
    SmemC& S = *reinterpret_cast<SmemC*>(sm);
    int tid = threadIdx.x;
    int rbase = blockIdx.x * TM;
    const float4 z4 = {0.f, 0.f, 0.f, 0.f};

    for (int i = tid; i < TM * DCn / 4; i += NT) {
        int r = i / (DCn / 4), c = i % (DCn / 4);
        int g = rbase + r;
        reinterpret_cast<float4*>(S.u)[i] = (g < E_Cn) ? reinterpret_cast<const float4*>(u + (size_t)g * DCn)[c] : z4;
    }
    if (tid < DMn) S.bcc[tid] = bcc[tid];
    if (tid < DHn) { S.bcs[tid] = bcs[tid]; S.bcm[tid] = bcm[tid]; }

    int tx = tid & 15, ty = tid >> 4;
    int j0 = tx * 8, n0l = ty * 2;

    // phase 1: sc = u @ (Wcc[:,:64] + Wcc[:,64:]).T + bcc
    {
        float t0[8], t1[8];
        #pragma unroll
        for (int i = 0; i < 8; i++) { t0[i] = 0.f; t1[i] = 0.f; }
        pair_mm(t0, t1, S.u, DCn, n0l, Wcc, 2 * DCn, 0, DCn, 64, S.w, j0, tid);
        #pragma unroll
        for (int i = 0; i < 8; i++) {
            S.sc[n0l * D + j0 + i]       = t0[i] + S.bcc[j0 + i];
            S.sc[(n0l + 1) * D + j0 + i] = t1[i] + S.bcc[j0 + i];
        }
    }

    // phase 2
    int g0 = rbase + n0l, g1 = g0 + 1;
    for (int jh = 0; jh < 2; jh++) {
        float a0[8], a1[8];
        #pragma unroll
        for (int i = 0; i < 8; i++) { a0[i] = 0.f; a1[i] = 0.f; }
        pair_mm(a0, a1, S.u,  DCn, n0l, Wcs + jh * 128 * DCn, DCn, 0, -1, 64,  S.w, j0, tid);
        pair_mm(a0, a1, S.sc, D,   n0l, Wcm + jh * 128 * D,   D,   0, -1, 128, S.w, j0, tid);
        int jo = jh * 128 + j0;
        if (g0 < E_Cn) {
            #pragma unroll
            for (int i = 0; i < 8; i++)
                out[(size_t)g0 * DHn + jo + i] = a0[i] + S.bcs[jo + i] + S.bcm[jo + i];
        }
        if (g1 < E_Cn) {
            #pragma unroll
            for (int i = 0; i < 8; i++)
                out[(size_t)g1 * DHn + jo + i] = a1[i] + S.bcs[jo + i] + S.bcm[jo + i];
        }
    }
}

// ---------------- launch ----------------
extern "C" void kernel_launch(void* const* d_in, const int* in_sizes, int n_in,
                              void* d_out, int out_size) {
    const float* x   = (const float*)d_in[0];
    const float* xb  = (const float*)d_in[1];
    const float* u   = (const float*)d_in[2];
    const int*   eiI = (const int*)d_in[3];
    const int*   eiB = (const int*)d_in[4];
    const int*   eiC = (const int*)d_in[5];
    const float* Wii = (const float*)d_in[8];
    const float* bii = (const float*)d_in[9];
    const float* Wbi = (const float*)d_in[10];
    const float* bbi = (const float*)d_in[11];
    const float* Wci = (const float*)d_in[12];
    const float* bci = (const float*)d_in[13];
    const float* Wbb = (const float*)d_in[14];
    const float* bbb = (const float*)d_in[15];
    const float* Wcc = (const float*)d_in[16];
    const float* bcc = (const float*)d_in[17];
    const float* Wim = (const float*)d_in[18];
    const float* bim = (const float*)d_in[19];
    const float* Wis = (const float*)d_in[20];
    const float* bis = (const float*)d_in[21];
    const float* Wbm = (const float*)d_in[22];
    const float* bbm = (const float*)d_in[23];
    const float* Wbs = (const float*)d_in[24];
    const float* bbs = (const float*)d_in[25];
    const float* Wcm = (const float*)d_in[26];
    const float* bcm = (const float*)d_in[27];
    const float* Wcs = (const float*)d_in[28];
    const float* bcs = (const float*)d_in[29];
    float* out = (float*)d_out;

    cudaFuncSetAttribute(k_interior, cudaFuncAttributeMaxDynamicSharedMemorySize, (int)sizeof(SmemInt));
    cudaFuncSetAttribute(k_boundary, cudaFuncAttributeMaxDynamicSharedMemorySize, (int)sizeof(SmemB));
    cudaFuncSetAttribute(k_control,  cudaFuncAttributeMaxDynamicSharedMemorySize, (int)sizeof(SmemC));

    k_zero<<<1024, 256>>>();
    k_scatter_int<<<(E_INTn * 32) / 256, 256>>>(eiI, x);
    k_scatter_b<<<(E_Bn * 32) / 256, 256>>>(eiB, xb);
    k_scatter_c<<<(E_Cn * 32) / 256, 256>>>(eiC, u);

    k_interior<<<(N_INTn + TM - 1) / TM, NT, sizeof(SmemInt)>>>(
        x, Wii, bii, Wbi, bbi, Wci, bci, Wim, bim, Wis, bis, out);
    k_boundary<<<(E_Bn + TM - 1) / TM, NT, sizeof(SmemB)>>>(
        xb, Wbb, bbb, Wbs, bbs, Wbm, bbm, out + (size_t)N_INTn * DHn);
    k_control<<<(E_Cn + TM - 1) / TM, NT, sizeof(SmemC)>>>(
        u, Wcc, bcc, Wcs, bcs, Wcm, bcm, out + (size_t)(N_INTn + E_Bn) * DHn);
}

// round 2
// speedup vs baseline: 2.1003x; 2.1003x over previous
#include <cuda_runtime.h>

// ---------------- problem constants ----------------
constexpr int N_INTn = 50000;
constexpr int D      = 128;
constexpr int DCn    = 64;
constexpr int E_INTn = 500000;
constexpr int E_Bn   = 20000;
constexpr int E_Cn   = 10000;

// ---------------- device scratch ----------------
__device__ float g_feat[N_INTn * 320];   // [aggS(128) | aggB(128) | aggC(64)]
__device__ float g_cntI[N_INTn], g_cntB[N_INTn], g_cntC[N_INTn];
__device__ float g_G1[N_INTn * 128];
__device__ float g_G2[N_INTn * 384];
__device__ float g_AGG[N_INTn * 128];
__device__ float g_sb[E_Bn * 128];
__device__ float g_sc[E_Cn * 128];
// packed weights
__device__ float g_W1[128 * 320];
__device__ float g_W2[384 * 128];
__device__ float g_WOI[256 * 256];
__device__ float g_WB1[128 * 128];
__device__ float g_WOB[256 * 256];
__device__ float g_WC1[128 * 64];
__device__ float g_WOC[256 * 192];
__device__ float g_bOI[256], g_bOB[256], g_bOC[256];

// ---------------- f32x2 packed math ----------------
#define FMA2(acc, a, b) asm("fma.rn.f32x2 %0, %1, %2, %0;" : "+l"(acc) : "l"(a), "l"(b))
#define PACK2(d, x)     asm("mov.b64 %0, {%1, %1};" : "=l"(d) : "f"(x))
#define UNPK2(lo, hi, v) asm("mov.b64 {%0, %1}, %2;" : "=f"(lo), "=f"(hi) : "l"(v))

// ---------------- generic fp32 GEMM: C = [A0|A1] @ W^T (+bias) ----------------
// A0: M x K0 row-major, A1: M x K1 row-major (K0, K1 multiples of 16; K1 may be 0)
// W:  N x (K0+K1) row-major (N = gridDim.y * 128)
// C:  M x ldc row-major, this grid writes cols [nbase, nbase+128)
__device__ __forceinline__ void load_a_frag(
    const float* __restrict__ A0, int K0, const float* __restrict__ A1, int K1,
    int mbase, int M, int lrow, int lc0, int kt, float4& a0, float4& a1)
{
    int kg = kt << 4;
    const float* src; int ld, ko;
    if (kg < K0) { src = A0; ld = K0; ko = kg; }
    else         { src = A1; ld = K1; ko = kg - K0; }
    int gm = mbase + lrow;
    if (gm < M) {
        const float* p = src + (size_t)gm * ld + ko + lc0;
        a0 = ((const float4*)p)[0];
        a1 = ((const float4*)p)[1];
    } else {
        a0 = make_float4(0.f, 0.f, 0.f, 0.f);
        a1 = a0;
    }
}

__global__ void __launch_bounds__(256) k_gemm(
    const float* __restrict__ A0, int K0,
    const float* __restrict__ A1, int K1,
    const float* __restrict__ W, const float* __restrict__ bias,
    float* __restrict__ C, int ldc, int M)
{
    __shared__ __align__(16) float As[2][16][128];
    __shared__ __align__(16) float Ws[2][16][128];

    const int tid   = threadIdx.x;
    const int mbase = blockIdx.x * 128;
    const int nbase = blockIdx.y * 128;
    const int Kt    = K0 + K1;
    const int nk    = Kt >> 4;
    const float* Wb = W + (size_t)nbase * Kt;

    const int lrow = tid >> 1;        // 0..127
    const int lc0  = (tid & 1) * 8;   // 0 or 8
    const int m0   = (tid >> 4) * 8;  // thread micro-tile row base
    const int n0   = (tid & 15) * 8;  // thread micro-tile col base

    unsigned long long acc[8][4];
    #pragma unroll
    for (int n = 0; n < 8; n++)
        #pragma unroll
        for (int mp = 0; mp < 4; mp++) acc[n][mp] = 0ull;

    float4 pa0, pa1, pw0, pw1;

    // prefetch + store tile 0
    load_a_frag(A0, K0, A1, K1, mbase, M, lrow, lc0, 0, pa0, pa1);
    {
        const float* q = Wb + (size_t)lrow * Kt + lc0;
        pw0 = ((const float4*)q)[0]; pw1 = ((const float4*)q)[1];
    }
    #pragma unroll
    for (int j = 0; j < 4; j++) {
        As[0][lc0 + j][lrow]     = (&pa0.x)[j];
        As[0][lc0 + 4 + j][lrow] = (&pa1.x)[j];
        Ws[0][lc0 + j][lrow]     = (&pw0.x)[j];
        Ws[0][lc0 + 4 + j][lrow] = (&pw1.x)[j];
    }
    __syncthreads();

    int buf = 0;
    for (int kt = 0; kt < nk; kt++) {
        const bool more = (kt + 1) < nk;
        if (more) {
            load_a_frag(A0, K0, A1, K1, mbase, M, lrow, lc0, kt + 1, pa0, pa1);
            const float* q = Wb + (size_t)lrow * Kt + ((kt + 1) << 4) + lc0;
            pw0 = ((const float4*)q)[0]; pw1 = ((const float4*)q)[1];
        }

        #pragma unroll
        for (int k = 0; k < 16; k++) {
            ulonglong2 av0 = *(const ulonglong2*)&As[buf][k][m0];
            ulonglong2 av1 = *(const ulonglong2*)&As[buf][k][m0 + 4];
            float4 w0 = *(const float4*)&Ws[buf][k][n0];
            float4 w1 = *(const float4*)&Ws[buf][k][n0 + 4];
            unsigned long long ap[4] = {av0.x, av0.y, av1.x, av1.y};
            unsigned long long wd[8];
            PACK2(wd[0], w0.x); PACK2(wd[1], w0.y); PACK2(wd[2], w0.z); PACK2(wd[3], w0.w);
            PACK2(wd[4], w1.x); PACK2(wd[5], w1.y); PACK2(wd[6], w1.z); PACK2(wd[7], w1.w);
            #pragma unroll
            for (int n = 0; n < 8; n++)
                #pragma unroll
                for (int mp = 0; mp < 4; mp++)
                    FMA2(acc[n][mp], ap[mp], wd[n]);
        }

        if (more) {
            int nb = buf ^ 1;
            #pragma unroll
            for (int j = 0; j < 4; j++) {
                As[nb][lc0 + j][lrow]     = (&pa0.x)[j];
                As[nb][lc0 + 4 + j][lrow] = (&pa1.x)[j];
                Ws[nb][lc0 + j][lrow]     = (&pw0.x)[j];
                Ws[nb][lc0 + 4 + j][lrow] = (&pw1.x)[j];
            }
        }
        __syncthreads();
        buf ^= 1;
    }

    // epilogue
    float bi[8];
    #pragma unroll
    for (int j = 0; j < 8; j++) bi[j] = bias ? bias[nbase + n0 + j] : 0.f;

    #pragma unroll
    for (int mp = 0; mp < 4; mp++) {
        float lo[8], hi[8];
        #pragma unroll
        for (int n = 0; n < 8; n++) UNPK2(lo[n], hi[n], acc[n][mp]);
        #pragma unroll
        for (int h = 0; h < 2; h++) {
            int gm = mbase + m0 + mp * 2 + h;
            if (gm < M) {
                const float* v = h ? hi : lo;
                float4 o0, o1;
                o0.x = v[0] + bi[0]; o0.y = v[1] + bi[1];
                o0.z = v[2] + bi[2]; o0.w = v[3] + bi[3];
                o1.x = v[4] + bi[4]; o1.y = v[5] + bi[5];
                o1.z = v[6] + bi[6]; o1.w = v[7] + bi[7];
                float4* dst = (float4*)(C + (size_t)gm * ldc + nbase + n0);
                dst[0] = o0; dst[1] = o1;
            }
        }
    }
}

// ---------------- weight packing ----------------
__global__ void k_pack(
    const float* __restrict__ Wii, const float* __restrict__ Wbi, const float* __restrict__ Wci,
    const float* __restrict__ Wbb, const float* __restrict__ Wcc,
    const float* __restrict__ Wis, const float* __restrict__ Wim,
    const float* __restrict__ Wbs, const float* __restrict__ Wbm,
    const float* __restrict__ Wcs, const float* __restrict__ Wcm,
    const float* __restrict__ bis, const float* __restrict__ bim,
    const float* __restrict__ bbs, const float* __restrict__ bbm,
    const float* __restrict__ bcs, const float* __restrict__ bcm)
{
    int i = blockIdx.x * blockDim.x + threadIdx.x;
    if (i < 40960) {                                  // W1: 128 x 320
        int j = i / 320, k = i % 320;
        float v;
        if (k < 128)      v = Wii[j * 256 + k];
        else if (k < 256) v = Wbi[j * 256 + (k - 128)];
        else              v = Wci[j * 192 + (k - 256)];
        g_W1[i] = v;
        return;
    }
    i -= 40960;
    if (i < 49152) {                                  // W2: 384 x 128
        int j = i / 128, k = i % 128;
        float v;
        if (j < 128)      v = Wii[j * 256 + 128 + k];
        else if (j < 256) v = Wbi[(j - 128) * 256 + 128 + k];
        else              v = Wci[(j - 256) * 192 + 64 + k];
        g_W2[i] = v;
        return;
    }
    i -= 49152;
    if (i < 65536) {                                  // WOI: 256 x 256
        int j = i / 256, k = i % 256;
        g_WOI[i] = (k < 128) ? Wis[j * 128 + k] : Wim[j * 128 + (k - 128)];
        return;
    }
    i -= 65536;
    if (i < 16384) {                                  // WB1: 128 x 128
        int j = i / 128, k = i % 128;
        g_WB1[i] = Wbb[j * 256 + k] + Wbb[j * 256 + 128 + k];
        return;
    }
    i -= 16384;
    if (i < 65536) {                                  // WOB: 256 x 256
        int j = i / 256, k = i % 256;
        g_WOB[i] = (k < 128) ? Wbs[j * 128 + k] : Wbm[j * 128 + (k - 128)];
        return;
    }
    i -= 65536;
    if (i < 8192) {                                   // WC1: 128 x 64
        int j = i / 64, k = i % 64;
        g_WC1[i] = Wcc[j * 128 + k] + Wcc[j * 128 + 64 + k];
        return;
    }
    i -= 8192;
    if (i < 49152) {                                  // WOC: 256 x 192
        int j = i / 192, k = i % 192;
        g_WOC[i] = (k < 64) ? Wcs[j * 64 + k] : Wcm[j * 128 + (k - 64)];
        return;
    }
    i -= 49152;
    if (i < 256) { g_bOI[i] = bis[i] + bim[i]; return; }
    i -= 256;
    if (i < 256) { g_bOB[i] = bbs[i] + bbm[i]; return; }
    i -= 256;
    if (i < 256) { g_bOC[i] = bcs[i] + bcm[i]; return; }
}

// ---------------- zero scratch ----------------
__global__ void k_zero() {
    int idx = blockIdx.x * blockDim.x + threadIdx.x;
    int stride = gridDim.x * blockDim.x;
    float4 z = {0.f, 0.f, 0.f, 0.f};
    float4* f = reinterpret_cast<float4*>(g_feat);
    for (int i = idx; i < N_INTn * 320 / 4; i += stride) f[i] = z;
    for (int i = idx; i < N_INTn; i += stride) {
        g_cntI[i] = 0.f; g_cntB[i] = 0.f; g_cntC[i] = 0.f;
    }
}

// ---------------- edge feature scatter (one warp per edge) ----------------
__device__ __forceinline__ void red4(float* p, float4 v) {
    asm volatile("red.global.add.v4.f32 [%0], {%1,%2,%3,%4};"
                 :: "l"(p), "f"(v.x), "f"(v.y), "f"(v.z), "f"(v.w) : "memory");
}

__global__ void k_scatter_int(const int* __restrict__ ei, const float* __restrict__ x) {
    int w = (blockIdx.x * blockDim.x + threadIdx.x) >> 5;
    int lane = threadIdx.x & 31;
    if (w >= E_INTn) return;
    int s = ei[w];
    int t = ei[E_INTn + w];
    float4 v = reinterpret_cast<const float4*>(x + (size_t)s * D)[lane];
    red4(g_feat + (size_t)t * 320 + lane * 4, v);
    if (lane == 0) atomicAdd(&g_cntI[t], 1.0f);
}

__global__ void k_scatter_b(const int* __restrict__ ei, const float* __restrict__ xb) {
    int w = (blockIdx.x * blockDim.x + threadIdx.x) >> 5;
    int lane = threadIdx.x & 31;
    if (w >= E_Bn) return;
    int t = ei[E_Bn + w];
    float4 v = reinterpret_cast<const float4*>(xb + (size_t)w * D)[lane];
    red4(g_feat + (size_t)t * 320 + 128 + lane * 4, v);
    if (lane == 0) atomicAdd(&g_cntB[t], 1.0f);
}

__global__ void k_scatter_c(const int* __restrict__ ei, const float* __restrict__ u) {
    int w = (blockIdx.x * blockDim.x + threadIdx.x) >> 5;
    int lane = threadIdx.x & 31;
    if (w >= E_Cn) return;
    int t = ei[E_Cn + w];
    if (lane < 16) {
        float4 v = reinterpret_cast<const float4*>(u + (size_t)w * DCn)[lane];
        red4(g_feat + (size_t)t * 320 + 256 + lane * 4, v);
    }
    if (lane == 0) atomicAdd(&g_cntC[t], 1.0f);
}

// ---------------- combine: AGG = (G1 + ci*(G2a+bii) + cb*(G2b+bbi) + cc*(G2c+bci)) / cnt ----
__global__ void k_combine(const float* __restrict__ bii, const float* __restrict__ bbi,
                          const float* __restrict__ bci) {
    int idx = blockIdx.x * blockDim.x + threadIdx.x;
    if (idx >= N_INTn * 32) return;
    int r = idx >> 5;
    int c = (idx & 31) * 4;
    float ci = g_cntI[r], cb = g_cntB[r], cc = g_cntC[r];
    float inv = 1.f / fmaxf(ci + cb + cc, 1.f);
    float4 g1 = *(const float4*)&g_G1[(size_t)r * 128 + c];
    const float* g2 = &g_G2[(size_t)r * 384];
    float4 a = *(const float4*)&g2[c];
    float4 b = *(const float4*)&g2[128 + c];
    float4 d = *(const float4*)&g2[256 + c];
    float4 v1 = *(const float4*)&bii[c];
    float4 v2 = *(const float4*)&bbi[c];
    float4 v3 = *(const float4*)&bci[c];
    float4 o;
    o.x = (g1.x + ci * (a.x + v1.x) + cb * (b.x + v2.x) + cc * (d.x + v3.x)) * inv;
    o.y = (g1.y + ci * (a.y + v1.y) + cb * (b.y + v2.y) + cc * (d.y + v3.y)) * inv;
    o.z = (g1.z + ci * (a.z + v1.z) + cb * (b.z + v2.z) + cc * (d.z + v3.z)) * inv;
    o.w = (g1.w + ci * (a.w + v1.w) + cb * (b.w + v2.w) + cc * (d.w + v3.w)) * inv;
    *(float4*)&g_AGG[(size_t)r * 128 + c] = o;
}

// ---------------- launch ----------------
static float* sym(const void* s) {
    void* p = nullptr;
    cudaGetSymbolAddress(&p, s);
    return (float*)p;
}

extern "C" void kernel_launch(void* const* d_in, const int* in_sizes, int n_in,
                              void* d_out, int out_size) {
    const float* x   = (const float*)d_in[0];
    const float* xb  = (const float*)d_in[1];
    const float* u   = (const float*)d_in[2];
    const int*   eiI = (const int*)d_in[3];
    const int*   eiB = (const int*)d_in[4];
    const int*   eiC = (const int*)d_in[5];
    const float* Wii = (const float*)d_in[8];
    const float* bii = (const float*)d_in[9];
    const float* Wbi = (const float*)d_in[10];
    const float* bbi = (const float*)d_in[11];
    const float* Wci = (const float*)d_in[12];
    const float* bci = (const float*)d_in[13];
    const float* Wbb = (const float*)d_in[14];
    const float* bbb = (const float*)d_in[15];
    const float* Wcc = (const float*)d_in[16];
    const float* bcc = (const float*)d_in[17];
    const float* Wim = (const float*)d_in[18];
    const float* bim = (const float*)d_in[19];
    const float* Wis = (const float*)d_in[20];
    const float* bis = (const float*)d_in[21];
    const float* Wbm = (const float*)d_in[22];
    const float* bbm = (const float*)d_in[23];
    const float* Wbs = (const float*)d_in[24];
    const float* bbs = (const float*)d_in[25];
    const float* Wcm = (const float*)d_in[26];
    const float* bcm = (const float*)d_in[27];
    const float* Wcs = (const float*)d_in[28];
    const float* bcs = (const float*)d_in[29];
    float* out = (float*)d_out;

    float* pFeat = sym(g_feat);
    float* pG1   = sym(g_G1);
    float* pG2   = sym(g_G2);
    float* pAGG  = sym(g_AGG);
    float* pSb   = sym(g_sb);
    float* pSc   = sym(g_sc);
    float* pW1   = sym(g_W1);
    float* pW2   = sym(g_W2);
    float* pWOI  = sym(g_WOI);
    float* pWB1  = sym(g_WB1);
    float* pWOB  = sym(g_WOB);
    float* pWC1  = sym(g_WC1);
    float* pWOC  = sym(g_WOC);
    float* pbOI  = sym(g_bOI);
    float* pbOB  = sym(g_bOB);
    float* pbOC  = sym(g_bOC);

    k_pack<<<(295680 + 255) / 256, 256>>>(Wii, Wbi, Wci, Wbb, Wcc, Wis, Wim,
                                          Wbs, Wbm, Wcs, Wcm,
                                          bis, bim, bbs, bbm, bcs, bcm);
    k_zero<<<1024, 256>>>();
    k_scatter_int<<<E_INTn * 32 / 256, 256>>>(eiI, x);
    k_scatter_b<<<E_Bn * 32 / 256, 256>>>(eiB, xb);
    k_scatter_c<<<E_Cn * 32 / 256, 256>>>(eiC, u);

    // interior
    k_gemm<<<dim3(391, 1), 256>>>(pFeat, 320, nullptr, 0, pW1, nullptr, pG1, 128, N_INTn);
    k_gemm<<<dim3(391, 3), 256>>>(x, 128, nullptr, 0, pW2, nullptr, pG2, 384, N_INTn);
    k_combine<<<(N_INTn * 32 + 255) / 256, 256>>>(bii, bbi, bci);
    k_gemm<<<dim3(391, 2), 256>>>(x, 128, pAGG, 128, pWOI, pbOI, out, 256, N_INTn);

    // boundary
    k_gemm<<<dim3(157, 1), 256>>>(xb, 128, nullptr, 0, pWB1, bbb, pSb, 128, E_Bn);
    k_gemm<<<dim3(157, 2), 256>>>(xb, 128, pSb, 128, pWOB, pbOB,
                                  out + (size_t)N_INTn * 256, 256, E_Bn);

    // control
    k_gemm<<<dim3(79, 1), 256>>>(u, 64, nullptr, 0, pWC1, bcc, pSc, 128, E_Cn);
    k_gemm<<<dim3(79, 2), 256>>>(u, 64, pSc, 128, pWOC, pbOC,
                                 out + (size_t)(N_INTn + E_Bn) * 256, 256, E_Cn);
}

// round 5
// speedup vs baseline: 2.4429x; 1.1631x over previous
#include <cuda_runtime.h>
#include <cuda_bf16.h>
#include <cstdint>
#include <cstddef>

// ---------------- problem constants ----------------
constexpr int N_INTn = 50000;
constexpr int D      = 128;
constexpr int DCn    = 64;
constexpr int E_INTn = 500000;
constexpr int E_Bn   = 20000;
constexpr int E_Cn   = 10000;
constexpr int NP_I   = 50048;   // 391*128
constexpr int NP_B   = 20096;   // 157*128
constexpr int NP_C   = 10112;   // 79*128

// ---------------- fp32 scratch ----------------
__device__ float g_feat[N_INTn * 320];
__device__ float g_cntI[N_INTn], g_cntB[N_INTn], g_cntC[N_INTn];
__device__ float g_G1[N_INTn * 128];
__device__ float g_G2[N_INTn * 384];
// packed fp32 weights
__device__ float g_W1[128 * 320];
__device__ float g_W2[384 * 128];
__device__ float g_WOI[256 * 256];
__device__ float g_WB1[128 * 128];
__device__ float g_WOB[256 * 256];
__device__ float g_WC1[128 * 64];
__device__ float g_WOC[256 * 192];
__device__ float g_bOI[256], g_bOB[256], g_bOC[256];

// ---------------- bf16 split-packed operands ([hi|hi|lo] rows, [hi|lo|hi] weights) ----
__device__ __align__(16) __nv_bfloat16 g_x3[NP_I * 384];
__device__ __align__(16) __nv_bfloat16 g_feat3[(size_t)NP_I * 960];
__device__ __align__(16) __nv_bfloat16 g_AGG3[NP_I * 384];
__device__ __align__(16) __nv_bfloat16 g_xb3[NP_B * 384];
__device__ __align__(16) __nv_bfloat16 g_sb3[NP_B * 384];
__device__ __align__(16) __nv_bfloat16 g_u3[NP_C * 192];
__device__ __align__(16) __nv_bfloat16 g_sc3[NP_C * 384];
__device__ __align__(16) __nv_bfloat16 g_W1_3[128 * 960];
__device__ __align__(16) __nv_bfloat16 g_W2_3[384 * 384];
__device__ __align__(16) __nv_bfloat16 g_WOI3[256 * 768];
__device__ __align__(16) __nv_bfloat16 g_WB13[128 * 384];
__device__ __align__(16) __nv_bfloat16 g_WOB3[256 * 768];
__device__ __align__(16) __nv_bfloat16 g_WC13[128 * 192];
__device__ __align__(16) __nv_bfloat16 g_WOC3[256 * 576];

// ---------------- PTX helpers (all baseline sm_80+ instructions) ----------------
__device__ __forceinline__ uint32_t cvta_s(const void* p) {
    uint32_t a;
    asm("{ .reg .u64 t; cvta.to.shared.u64 t, %1; cvt.u32.u64 %0, t; }" : "=r"(a) : "l"(p));
    return a;
}
#define CPA16(dst, src) asm volatile("cp.async.cg.shared.global [%0], [%1], 16;" :: "r"(dst), "l"(src))
#define CPCOMMIT()      asm volatile("cp.async.commit_group;" ::: "memory")
#define CPWAIT1()       asm volatile("cp.async.wait_group 1;" ::: "memory")

#define LDSM4(r0, r1, r2, r3, a) \
    asm volatile("ldmatrix.sync.aligned.m8n8.x4.shared.b16 {%0,%1,%2,%3}, [%4];" \
                 : "=r"(r0), "=r"(r1), "=r"(r2), "=r"(r3) : "r"(a))

#define MMA16816(c, av, b0, b1) \
    asm volatile("mma.sync.aligned.m16n8k16.row.col.f32.bf16.bf16.f32 " \
                 "{%0,%1,%2,%3}, {%4,%5,%6,%7}, {%8,%9}, {%0,%1,%2,%3};" \
                 : "+f"((c)[0]), "+f"((c)[1]), "+f"((c)[2]), "+f"((c)[3]) \
                 : "r"((av)[0]), "r"((av)[1]), "r"((av)[2]), "r"((av)[3]), \
                   "r"(b0), "r"(b1))

__device__ __forceinline__ uint32_t pack_bf2(float a, float b) {
    __nv_bfloat162 t;
    t.x = __float2bfloat16_rn(a);
    t.y = __float2bfloat16_rn(b);
    return *reinterpret_cast<uint32_t*>(&t);
}

// ---------------- mma.sync GEMM: C = [A0|A1] @ W^T (+bias) ----------------
// CTA tile 128x128, 8 warps (4m x 2n), k-tile 32, padded smem rows (40 bf16).
constexpr int KPAD = 40;                      // padded row length (bf16)
constexpr int TILE_B = 128 * KPAD;            // elements per buffer

__device__ __forceinline__ void issue_tile(
    uint32_t as_b, uint32_t bs_b, int buf, int kt,
    const __nv_bfloat16* A0, int K0, const __nv_bfloat16* A1, int K1,
    const __nv_bfloat16* W, int Kt, int mbase, int nbase, int tid)
{
    int kc = kt << 5;                         // 32 k per tile
    const __nv_bfloat16* Asrc;
    int lda, ko;
    if (kc < K0) { Asrc = A0 + (size_t)mbase * K0; lda = K0; ko = kc; }
    else         { Asrc = A1 + (size_t)mbase * K1; lda = K1; ko = kc - K0; }
    const __nv_bfloat16* Wsrc = W + (size_t)nbase * Kt + kc;
    uint32_t ab = as_b + buf * (TILE_B * 2);
    uint32_t bb = bs_b + buf * (TILE_B * 2);
    #pragma unroll
    for (int r = 0; r < 2; r++) {
        int chunk = tid + r * 256;            // 0..511
        int row = chunk >> 2, c16 = chunk & 3;
        uint32_t off = (row * KPAD + c16 * 8) * 2;
        CPA16(ab + off, Asrc + (size_t)row * lda + ko + c16 * 8);
        CPA16(bb + off, Wsrc + (size_t)row * Kt + c16 * 8);
    }
}

__global__ void __launch_bounds__(256, 2) k_gemm_mma(
    const __nv_bfloat16* __restrict__ A0, int K0,
    const __nv_bfloat16* __restrict__ A1, int K1,
    const __nv_bfloat16* __restrict__ W,
    const float* __restrict__ bias,
    float* __restrict__ C, int ldc, int M,
    __nv_bfloat16* __restrict__ D3, int Ntot)
{
    __shared__ __align__(16) __nv_bfloat16 As[2][128][KPAD];
    __shared__ __align__(16) __nv_bfloat16 Bs[2][128][KPAD];
    __shared__ float bsm[128];

    const int tid  = threadIdx.x;
    const int wid  = tid >> 5;
    const int lane = tid & 31;
    const int wm   = wid >> 1;                // 0..3 (m block of 32 rows)
    const int wn   = wid & 1;                 // 0..1 (n block of 64 cols)
    const int mbase = blockIdx.x * 128;
    const int nbase = blockIdx.y * 128;
    const int Kt = K0 + K1;
    const int nk = Kt >> 5;

    if (tid < 128) bsm[tid] = bias ? bias[nbase + tid] : 0.f;

    uint32_t as_b = cvta_s(&As[0][0][0]);
    uint32_t bs_b = cvta_s(&Bs[0][0][0]);

    // per-thread ldmatrix base addresses (buf 0, k16 step 0)
    // A: row = wm*32 + (lane%16), col = 8*(lane/16)
    uint32_t a_addr = as_b + (((wm * 32 + (lane & 15)) * KPAD + (lane >> 4) * 8) * 2);
    // B: jj=lane/8: row = wn*64 + (jj>=2)*8 + (lane%8), col = (jj&1)*8
    int jj = lane >> 3;
    uint32_t b_addr = bs_b + (((wn * 64 + ((jj >> 1) * 8) + (lane & 7)) * KPAD + (jj & 1) * 8) * 2);

    float acc[2][8][4];
    #pragma unroll
    for (int mt = 0; mt < 2; mt++)
        #pragma unroll
        for (int nt = 0; nt < 8; nt++)
            #pragma unroll
            for (int j = 0; j < 4; j++) acc[mt][nt][j] = 0.f;

    issue_tile(as_b, bs_b, 0, 0, A0, K0, A1, K1, W, Kt, mbase, nbase, tid);
    CPCOMMIT();
    if (nk > 1)
        issue_tile(as_b, bs_b, 1, 1, A0, K0, A1, K1, W, Kt, mbase, nbase, tid);
    CPCOMMIT();

    for (int kt = 0; kt < nk; kt++) {
        int buf = kt & 1;
        CPWAIT1();
        __syncthreads();
        uint32_t boff = buf * (TILE_B * 2);
        #pragma unroll
        for (int s = 0; s < 2; s++) {
            uint32_t koff = boff + s * 32;    // 16 bf16 = 32 B
            uint32_t a[2][4];
            #pragma unroll
            for (int mt = 0; mt < 2; mt++)
                LDSM4(a[mt][0], a[mt][1], a[mt][2], a[mt][3],
                      a_addr + koff + mt * (16 * KPAD * 2));
            uint32_t b[8][2];
            #pragma unroll
            for (int g = 0; g < 4; g++) {
                uint32_t r0, r1, r2, r3;
                LDSM4(r0, r1, r2, r3, b_addr + koff + g * (16 * KPAD * 2));
                b[g * 2][0] = r0; b[g * 2][1] = r1;
                b[g * 2 + 1][0] = r2; b[g * 2 + 1][1] = r3;
            }
            #pragma unroll
            for (int mt = 0; mt < 2; mt++)
                #pragma unroll
                for (int nt = 0; nt < 8; nt++)
                    MMA16816(acc[mt][nt], a[mt], b[nt][0], b[nt][1]);
        }
        __syncthreads();
        if (kt + 2 < nk)
            issue_tile(as_b, bs_b, buf, kt + 2, A0, K0, A1, K1, W, Kt, mbase, nbase, tid);
        CPCOMMIT();
    }

    // ---- epilogue ----
    #pragma unroll
    for (int mt = 0; mt < 2; mt++) {
        #pragma unroll
        for (int nt = 0; nt < 8; nt++) {
            int ml = wm * 32 + mt * 16 + (lane >> 2);
            int nl = wn * 64 + nt * 8 + (lane & 3) * 2;
            float b0 = bsm[nl], b1 = bsm[nl + 1];
            float v00 = acc[mt][nt][0] + b0, v01 = acc[mt][nt][1] + b1;
            float v10 = acc[mt][nt][2] + b0, v11 = acc[mt][nt][3] + b1;
            int gm0 = mbase + ml, gm1 = gm0 + 8;
            if (C) {
                if (gm0 < M) {
                    float2 o = {v00, v01};
                    *reinterpret_cast<float2*>(C + (size_t)gm0 * ldc + nbase + nl) = o;
                }
                if (gm1 < M) {
                    float2 o = {v10, v11};
                    *reinterpret_cast<float2*>(C + (size_t)gm1 * ldc + nbase + nl) = o;
                }
            } else {
                // bf16 split-pack rows: [hi | hi | lo]
                __nv_bfloat16 h00 = __float2bfloat16_rn(v00);
                __nv_bfloat16 h01 = __float2bfloat16_rn(v01);
                __nv_bfloat16 h10 = __float2bfloat16_rn(v10);
                __nv_bfloat16 h11 = __float2bfloat16_rn(v11);
                uint32_t hp0 = pack_bf2(v00, v01);
                uint32_t lp0 = pack_bf2(v00 - __bfloat162float(h00),
                                        v01 - __bfloat162float(h01));
                uint32_t hp1 = pack_bf2(v10, v11);
                uint32_t lp1 = pack_bf2(v10 - __bfloat162float(h10),
                                        v11 - __bfloat162float(h11));
                __nv_bfloat16* r0 = D3 + (size_t)gm0 * (3 * Ntot) + nbase + nl;
                __nv_bfloat16* r1 = D3 + (size_t)gm1 * (3 * Ntot) + nbase + nl;
                *reinterpret_cast<uint32_t*>(r0) = hp0;
                *reinterpret_cast<uint32_t*>(r0 + Ntot) = hp0;
                *reinterpret_cast<uint32_t*>(r0 + 2 * Ntot) = lp0;
                *reinterpret_cast<uint32_t*>(r1) = hp1;
                *reinterpret_cast<uint32_t*>(r1 + Ntot) = hp1;
                *reinterpret_cast<uint32_t*>(r1 + 2 * Ntot) = lp1;
            }
        }
    }
}

// ---------------- weight packing (fp32) ----------------
__global__ void k_pack(
    const float* __restrict__ Wii, const float* __restrict__ Wbi, const float* __restrict__ Wci,
    const float* __restrict__ Wbb, const float* __restrict__ Wcc,
    const float* __restrict__ Wis, const float* __restrict__ Wim,
    const float* __restrict__ Wbs, const float* __restrict__ Wbm,
    const float* __restrict__ Wcs, const float* __restrict__ Wcm,
    const float* __restrict__ bis, const float* __restrict__ bim,
    const float* __restrict__ bbs, const float* __restrict__ bbm,
    const float* __restrict__ bcs, const float* __restrict__ bcm)
{
    int i = blockIdx.x * blockDim.x + threadIdx.x;
    if (i < 40960) {  // W1: 128 x 320
        int j = i / 320, k = i % 320;
        float v;
        if (k < 128)      v = Wii[j * 256 + k];
        else if (k < 256) v = Wbi[j * 256 + (k - 128)];
        else              v = Wci[j * 192 + (k - 256)];
        g_W1[i] = v; return;
    }
    i -= 40960;
    if (i < 49152) {  // W2: 384 x 128
        int j = i / 128, k = i % 128;
        float v;
        if (j < 128)      v = Wii[j * 256 + 128 + k];
        else if (j < 256) v = Wbi[(j - 128) * 256 + 128 + k];
        else              v = Wci[(j - 256) * 192 + 64 + k];
        g_W2[i] = v; return;
    }
    i -= 49152;
    if (i < 65536) {  // WOI: 256 x 256
        int j = i / 256, k = i % 256;
        g_WOI[i] = (k < 128) ? Wis[j * 128 + k] : Wim[j * 128 + (k - 128)];
        return;
    }
    i -= 65536;
    if (i < 16384) {  // WB1: 128 x 128
        int j = i / 128, k = i % 128;
        g_WB1[i] = Wbb[j * 256 + k] + Wbb[j * 256 + 128 + k];
        return;
    }
    i -= 16384;
    if (i < 65536) {  // WOB: 256 x 256
        int j = i / 256, k = i % 256;
        g_WOB[i] = (k < 128) ? Wbs[j * 128 + k] : Wbm[j * 128 + (k - 128)];
        return;
    }
    i -= 65536;
    if (i < 8192) {   // WC1: 128 x 64
        int j = i / 64, k = i % 64;
        g_WC1[i] = Wcc[j * 128 + k] + Wcc[j * 128 + 64 + k];
        return;
    }
    i -= 8192;
    if (i < 49152) {  // WOC: 256 x 192
        int j = i / 192, k = i % 192;
        g_WOC[i] = (k < 64) ? Wcs[j * 64 + k] : Wcm[j * 128 + (k - 64)];
        return;
    }
    i -= 49152;
    if (i < 256) { g_bOI[i] = bis[i] + bim[i]; return; }
    i -= 256;
    if (i < 256) { g_bOB[i] = bbs[i] + bbm[i]; return; }
    i -= 256;
    if (i < 256) { g_bOC[i] = bcs[i] + bcm[i]; return; }
}

// ---------------- weight bf16 split: dst block = [hi | lo | hi] ----------------
__global__ void k_w3(const float* __restrict__ src, int srcLd, int srcOff,
                     __nv_bfloat16* __restrict__ dst, int dstLd, int dstOff,
                     int N, int K)
{
    int idx = blockIdx.x * blockDim.x + threadIdx.x;
    if (idx >= N * 3 * K) return;
    int n = idx / (3 * K);
    int c3 = idx % (3 * K);
    int seg = c3 / K, k = c3 % K;
    float v = src[(size_t)n * srcLd + srcOff + k];
    __nv_bfloat16 hi = __float2bfloat16_rn(v);
    dst[(size_t)n * dstLd + dstOff + c3] =
        (seg == 1) ? __float2bfloat16_rn(v - __bfloat162float(hi)) : hi;
}

// ---------------- A split: dst row = [hi | hi | lo] ----------------
__global__ void k_a3(const float* __restrict__ src, __nv_bfloat16* __restrict__ dst,
                     int M, int Mpad, int K)
{
    int K3 = 3 * K;
    int idx = blockIdx.x * blockDim.x + threadIdx.x;   // per 8 outputs
    int total = Mpad * (K3 >> 3);
    if (idx >= total) return;
    int m = idx / (K3 >> 3);
    int c3 = (idx % (K3 >> 3)) << 3;
    int seg = c3 / K, k = c3 % K;
    float v[8];
    if (m < M) {
        const float* p = src + (size_t)m * K + k;
        float4 a = ((const float4*)p)[0], b = ((const float4*)p)[1];
        v[0]=a.x; v[1]=a.y; v[2]=a.z; v[3]=a.w; v[4]=b.x; v[5]=b.y; v[6]=b.z; v[7]=b.w;
    } else {
        #pragma unroll
        for (int j = 0; j < 8; j++) v[j] = 0.f;
    }
    __nv_bfloat16 o[8];
    #pragma unroll
    for (int j = 0; j < 8; j++) {
        __nv_bfloat16 hi = __float2bfloat16_rn(v[j]);
        o[j] = (seg == 2) ? __float2bfloat16_rn(v[j] - __bfloat162float(hi)) : hi;
    }
    *(uint4*)(dst + (size_t)m * K3 + c3) = *(const uint4*)o;
}

// ---------------- zero scratch ----------------
__global__ void k_zero() {
    int idx = blockIdx.x * blockDim.x + threadIdx.x;
    int stride = gridDim.x * blockDim.x;
    float4 z = {0.f, 0.f, 0.f, 0.f};
    float4* f = reinterpret_cast<float4*>(g_feat);
    for (int i = idx; i < N_INTn * 320 / 4; i += stride) f[i] = z;
    for (int i = idx; i < N_INTn; i += stride) {
        g_cntI[i] = 0.f; g_cntB[i] = 0.f; g_cntC[i] = 0.f;
    }
}

// ---------------- edge scatter: 4 edges per warp, loads grouped ----------------
__device__ __forceinline__ void red4(float* p, float4 v) {
    asm volatile("red.global.add.v4.f32 [%0], {%1,%2,%3,%4};"
                 :: "l"(p), "f"(v.x), "f"(v.y), "f"(v.z), "f"(v.w) : "memory");
}

__global__ void k_scatter_int(const int* __restrict__ ei, const float* __restrict__ x) {
    int w = (blockIdx.x * blockDim.x + threadIdx.x) >> 5;
    int lane = threadIdx.x & 31;
    int e0 = w * 4;
    int s[4], t[4];
    #pragma unroll
    for (int j = 0; j < 4; j++) { s[j] = ei[e0 + j]; t[j] = ei[E_INTn + e0 + j]; }
    float4 v[4];
    #pragma unroll
    for (int j = 0; j < 4; j++)
        v[j] = ((const float4*)(x + (size_t)s[j] * D))[lane];
    #pragma unroll
    for (int j = 0; j < 4; j++)
        red4(g_feat + (size_t)t[j] * 320 + lane * 4, v[j]);
    if (lane == 0) {
        #pragma unroll
        for (int j = 0; j < 4; j++) atomicAdd(&g_cntI[t[j]], 1.0f);
    }
}

__global__ void k_scatter_b(const int* __restrict__ ei, const float* __restrict__ xb) {
    int w = (blockIdx.x * blockDim.x + threadIdx.x) >> 5;
    int lane = threadIdx.x & 31;
    int e0 = w * 4;
    int t[4];
    #pragma unroll
    for (int j = 0; j < 4; j++) t[j] = ei[E_Bn + e0 + j];
    float4 v[4];
    #pragma unroll
    for (int j = 0; j < 4; j++)
        v[j] = ((const float4*)(xb + (size_t)(e0 + j) * D))[lane];
    #pragma unroll
    for (int j = 0; j < 4; j++)
        red4(g_feat + (size_t)t[j] * 320 + 128 + lane * 4, v[j]);
    if (lane == 0) {
        #pragma unroll
        for (int j = 0; j < 4; j++) atomicAdd(&g_cntB[t[j]], 1.0f);
    }
}

__global__ void k_scatter_c(const int* __restrict__ ei, const float* __restrict__ u) {
    int w = (blockIdx.x * blockDim.x + threadIdx.x) >> 5;
    int lane = threadIdx.x & 31;
    if (w >= E_Cn / 4) return;
    int e0 = w * 4;
    int t[4];
    #pragma unroll
    for (int j = 0; j < 4; j++) t[j] = ei[E_Cn + e0 + j];
    if (lane < 16) {
        float4 v[4];
        #pragma unroll
        for (int j = 0; j < 4; j++)
            v[j] = ((const float4*)(u + (size_t)(e0 + j) * DCn))[lane];
        #pragma unroll
        for (int j = 0; j < 4; j++)
            red4(g_feat + (size_t)t[j] * 320 + 256 + lane * 4, v[j]);
    }
    if (lane == 0) {
        #pragma unroll
        for (int j = 0; j < 4; j++) atomicAdd(&g_cntC[t[j]], 1.0f);
    }
}

// ---------------- combine -> AGG3 (bf16 split-pack) ----------------
__global__ void k_combine(const float* __restrict__ bii, const float* __restrict__ bbi,
                          const float* __restrict__ bci) {
    int idx = blockIdx.x * blockDim.x + threadIdx.x;
    if (idx >= NP_I * 32) return;
    int r = idx >> 5;
    int c = (idx & 31) * 4;
    float o[4] = {0.f, 0.f, 0.f, 0.f};
    if (r < N_INTn) {
        float ci = g_cntI[r], cb = g_cntB[r], cc = g_cntC[r];
        float inv = 1.f / fmaxf(ci + cb + cc, 1.f);
        float4 g1 = *(const float4*)&g_G1[(size_t)r * 128 + c];
        const float* g2 = &g_G2[(size_t)r * 384];
        float4 a = *(const float4*)&g2[c];
        float4 b = *(const float4*)&g2[128 + c];
        float4 d = *(const float4*)&g2[256 + c];
        float4 v1 = *(const float4*)&bii[c];
        float4 v2 = *(const float4*)&bbi[c];
        float4 v3 = *(const float4*)&bci[c];
        o[0] = (g1.x + ci * (a.x + v1.x) + cb * (b.x + v2.x) + cc * (d.x + v3.x)) * inv;
        o[1] = (g1.y + ci * (a.y + v1.y) + cb * (b.y + v2.y) + cc * (d.y + v3.y)) * inv;
        o[2] = (g1.z + ci * (a.z + v1.z) + cb * (b.z + v2.z) + cc * (d.z + v3.z)) * inv;
        o[3] = (g1.w + ci * (a.w + v1.w) + cb * (b.w + v2.w) + cc * (d.w + v3.w)) * inv;
    }
    __nv_bfloat16 hi[4], lo[4];
    #pragma unroll
    for (int j = 0; j < 4; j++) {
        hi[j] = __float2bfloat16_rn(o[j]);
        lo[j] = __float2bfloat16_rn(o[j] - __bfloat162float(hi[j]));
    }
    __nv_bfloat16* row = g_AGG3 + (size_t)r * 384;
    *(uint2*)(row + c)       = *(const uint2*)hi;
    *(uint2*)(row + 128 + c) = *(const uint2*)hi;
    *(uint2*)(row + 256 + c) = *(const uint2*)lo;
}

// ---------------- launch ----------------
static void* symv(const void* s) { void* p = nullptr; cudaGetSymbolAddress(&p, s); return p; }

extern "C" void kernel_launch(void* const* d_in, const int* in_sizes, int n_in,
                              void* d_out, int out_size) {
    const float* x   = (const float*)d_in[0];
    const float* xb  = (const float*)d_in[1];
    const float* u   = (const float*)d_in[2];
    const int*   eiI = (const int*)d_in[3];
    const int*   eiB = (const int*)d_in[4];
    const int*   eiC = (const int*)d_in[5];
    const float* Wii = (const float*)d_in[8];
    const float* bii = (const float*)d_in[9];
    const float* Wbi = (const float*)d_in[10];
    const float* bbi = (const float*)d_in[11];
    const float* Wci = (const float*)d_in[12];
    const float* bci = (const float*)d_in[13];
    const float* Wbb = (const float*)d_in[14];
    const float* bbb = (const float*)d_in[15];
    const float* Wcc = (const float*)d_in[16];
    const float* bcc = (const float*)d_in[17];
    const float* Wim = (const float*)d_in[18];
    const float* bim = (const float*)d_in[19];
    const float* Wis = (const float*)d_in[20];
    const float* bis = (const float*)d_in[21];
    const float* Wbm = (const float*)d_in[22];
    const float* bbm = (const float*)d_in[23];
    const float* Wbs = (const float*)d_in[24];
    const float* bbs = (const float*)d_in[25];
    const float* Wcm = (const float*)d_in[26];
    const float* bcm = (const float*)d_in[27];
    const float* Wcs = (const float*)d_in[28];
    const float* bcs = (const float*)d_in[29];
    float* out = (float*)d_out;

    const float* pW1  = (const float*)symv(g_W1);
    const float* pW2  = (const float*)symv(g_W2);
    const float* pWOI = (const float*)symv(g_WOI);
    const float* pWB1 = (const float*)symv(g_WB1);
    const float* pWOB = (const float*)symv(g_WOB);
    const float* pWC1 = (const float*)symv(g_WC1);
    const float* pWOC = (const float*)symv(g_WOC);
    const float* pbOI = (const float*)symv(g_bOI);
    const float* pbOB = (const float*)symv(g_bOB);
    const float* pbOC = (const float*)symv(g_bOC);
    const float* pFeat = (const float*)symv(g_feat);
    float* pG1 = (float*)symv(g_G1);
    float* pG2 = (float*)symv(g_G2);
    __nv_bfloat16* px3   = (__nv_bfloat16*)symv(g_x3);
    __nv_bfloat16* pfeat3= (__nv_bfloat16*)symv(g_feat3);
    __nv_bfloat16* pAGG3 = (__nv_bfloat16*)symv(g_AGG3);
    __nv_bfloat16* pxb3  = (__nv_bfloat16*)symv(g_xb3);
    __nv_bfloat16* psb3  = (__nv_bfloat16*)symv(g_sb3);
    __nv_bfloat16* pu3   = (__nv_bfloat16*)symv(g_u3);
    __nv_bfloat16* psc3  = (__nv_bfloat16*)symv(g_sc3);
    __nv_bfloat16* pW1_3 = (__nv_bfloat16*)symv(g_W1_3);
    __nv_bfloat16* pW2_3 = (__nv_bfloat16*)symv(g_W2_3);
    __nv_bfloat16* pWOI3 = (__nv_bfloat16*)symv(g_WOI3);
    __nv_bfloat16* pWB13 = (__nv_bfloat16*)symv(g_WB13);
    __nv_bfloat16* pWOB3 = (__nv_bfloat16*)symv(g_WOB3);
    __nv_bfloat16* pWC13 = (__nv_bfloat16*)symv(g_WC13);
    __nv_bfloat16* pWOC3 = (__nv_bfloat16*)symv(g_WOC3);

    k_pack<<<(295680 + 255) / 256, 256>>>(Wii, Wbi, Wci, Wbb, Wcc, Wis, Wim,
                                          Wbs, Wbm, Wcs, Wcm,
                                          bis, bim, bbs, bbm, bcs, bcm);
    // weight splits
    auto w3 = [](const float* s, int sld, int soff, __nv_bfloat16* d, int dld, int doff,
                 int N, int K) {
        int n = N * 3 * K;
        k_w3<<<(n + 255) / 256, 256>>>(s, sld, soff, d, dld, doff, N, K);
    };
    w3(pW1, 320, 0, pW1_3, 960, 0, 128, 320);
    w3(pW2, 128, 0, pW2_3, 384, 0, 384, 128);
    w3(pWOI, 256, 0,   pWOI3, 768, 0,   256, 128);
    w3(pWOI, 256, 128, pWOI3, 768, 384, 256, 128);
    w3(pWB1, 128, 0, pWB13, 384, 0, 128, 128);
    w3(pWOB, 256, 0,   pWOB3, 768, 0,   256, 128);
    w3(pWOB, 256, 128, pWOB3, 768, 384, 256, 128);
    w3(pWC1, 64, 0, pWC13, 192, 0, 128, 64);
    w3(pWOC, 192, 0,  pWOC3, 576, 0,   256, 64);
    w3(pWOC, 192, 64, pWOC3, 576, 192, 256, 128);

    k_zero<<<1024, 256>>>();
    k_scatter_int<<<E_INTn / 32, 256>>>(eiI, x);
    k_scatter_b<<<E_Bn / 32, 256>>>(eiB, xb);
    k_scatter_c<<<(E_Cn / 4 * 32 + 255) / 256, 256>>>(eiC, u);

    // A splits
    k_a3<<<(NP_I * 48 + 255) / 256, 256>>>(x, px3, N_INTn, NP_I, 128);
    k_a3<<<(NP_B * 48 + 255) / 256, 256>>>(xb, pxb3, E_Bn, NP_B, 128);
    k_a3<<<(NP_C * 24 + 255) / 256, 256>>>(u, pu3, E_Cn, NP_C, 64);
    k_a3<<<((size_t)NP_I * 120 + 255) / 256, 256>>>(pFeat, pfeat3, N_INTn, NP_I, 320);

    // interior
    k_gemm_mma<<<dim3(391, 1), 256>>>(pfeat3, 960, nullptr, 0, pW1_3,
                                      nullptr, pG1, 128, N_INTn, nullptr, 0);
    k_gemm_mma<<<dim3(391, 3), 256>>>(px3, 384, nullptr, 0, pW2_3,
                                      nullptr, pG2, 384, N_INTn, nullptr, 0);
    k_combine<<<(NP_I * 32 + 255) / 256, 256>>>(bii, bbi, bci);
    k_gemm_mma<<<dim3(391, 2), 256>>>(px3, 384, pAGG3, 384, pWOI3,
                                      pbOI, out, 256, N_INTn, nullptr, 0);
    // boundary
    k_gemm_mma<<<dim3(157, 1), 256>>>(pxb3, 384, nullptr, 0, pWB13,
                                      bbb, nullptr, 0, 0, psb3, 128);
    k_gemm_mma<<<dim3(157, 2), 256>>>(pxb3, 384, psb3, 384, pWOB3,
                                      pbOB, out + (size_t)N_INTn * 256, 256, E_Bn,
                                      nullptr, 0);
    // control
    k_gemm_mma<<<dim3(79, 1), 256>>>(pu3, 192, nullptr, 0, pWC13,
                                     bcc, nullptr, 0, 0, psc3, 128);
    k_gemm_mma<<<dim3(79, 2), 256>>>(pu3, 192, psc3, 384, pWOC3,
                                     pbOC, out + (size_t)(N_INTn + E_Bn) * 256, 256,
                                     E_Cn, nullptr, 0);
}

// round 6
// speedup vs baseline: 3.9902x; 1.6334x over previous
#include <cuda_runtime.h>
#include <cuda_bf16.h>
#include <cstdint>
#include <cstddef>

// ---------------- problem constants ----------------
constexpr int N_INTn = 50000;
constexpr int D      = 128;
constexpr int DCn    = 64;
constexpr int E_INTn = 500000;
constexpr int E_Bn   = 20000;
constexpr int E_Cn   = 10000;
constexpr int NP_I   = 50048;   // 391*128
constexpr int NP_B   = 20096;   // 157*128
constexpr int NP_C   = 10112;   // 79*128
constexpr int KFE    = 704;     // featext K

// ---------------- fp32 scratch ----------------
__device__ float g_feat[N_INTn * 320];
__device__ float g_cntI[N_INTn], g_cntB[N_INTn], g_cntC[N_INTn];
__device__ float g_bOI[256], g_bOB[256], g_bOC[256];

// ---------------- bf16 hi/lo planes ----------------
__device__ __align__(16) __nv_bfloat16 g_xh[NP_I * 128],  g_xl[NP_I * 128];
__device__ __align__(16) __nv_bfloat16 g_xbh[NP_B * 128], g_xbl[NP_B * 128];
__device__ __align__(16) __nv_bfloat16 g_uh[NP_C * 64],   g_ul[NP_C * 64];
__device__ __align__(16) __nv_bfloat16 g_feh[(size_t)NP_I * KFE], g_fel[(size_t)NP_I * KFE];
__device__ __align__(16) __nv_bfloat16 g_aggh[NP_I * 128], g_aggl[NP_I * 128];
__device__ __align__(16) __nv_bfloat16 g_sbh[NP_B * 128],  g_sbl[NP_B * 128];
__device__ __align__(16) __nv_bfloat16 g_sch[NP_C * 128],  g_scl[NP_C * 128];
// weight planes
__device__ __align__(16) __nv_bfloat16 g_W1h[128 * KFE], g_W1l[128 * KFE];
__device__ __align__(16) __nv_bfloat16 g_WOIh[256 * 256], g_WOIl[256 * 256];
__device__ __align__(16) __nv_bfloat16 g_WB1h[128 * 128], g_WB1l[128 * 128];
__device__ __align__(16) __nv_bfloat16 g_WOBh[256 * 256], g_WOBl[256 * 256];
__device__ __align__(16) __nv_bfloat16 g_WC1h[128 * 64],  g_WC1l[128 * 64];
__device__ __align__(16) __nv_bfloat16 g_WOCh[256 * 192], g_WOCl[256 * 192];

// ---------------- PTX helpers ----------------
__device__ __forceinline__ uint32_t cvta_s(const void* p) {
    uint32_t a;
    asm("{ .reg .u64 t; cvta.to.shared.u64 t, %1; cvt.u32.u64 %0, t; }" : "=r"(a) : "l"(p));
    return a;
}
#define CPA16(dst, src) asm volatile("cp.async.cg.shared.global [%0], [%1], 16;" :: "r"(dst), "l"(src))
#define CPCOMMIT()      asm volatile("cp.async.commit_group;" ::: "memory")
#define CPWAIT1()       asm volatile("cp.async.wait_group 1;" ::: "memory")

#define LDSM4(r0, r1, r2, r3, a) \
    asm volatile("ldmatrix.sync.aligned.m8n8.x4.shared.b16 {%0,%1,%2,%3}, [%4];" \
                 : "=r"(r0), "=r"(r1), "=r"(r2), "=r"(r3) : "r"(a))

#define MMA16816(c, av, b0, b1) \
    asm volatile("mma.sync.aligned.m16n8k16.row.col.f32.bf16.bf16.f32 " \
                 "{%0,%1,%2,%3}, {%4,%5,%6,%7}, {%8,%9}, {%0,%1,%2,%3};" \
                 : "+f"((c)[0]), "+f"((c)[1]), "+f"((c)[2]), "+f"((c)[3]) \
                 : "r"((av)[0]), "r"((av)[1]), "r"((av)[2]), "r"((av)[3]), \
                   "r"(b0), "r"(b1))

__device__ __forceinline__ uint32_t pack_bf2(float a, float b) {
    __nv_bfloat162 t;
    t.x = __float2bfloat16_rn(a);
    t.y = __float2bfloat16_rn(b);
    return *reinterpret_cast<uint32_t*>(&t);
}
__device__ __forceinline__ uint32_t pack_lo2(float a, float b) {
    __nv_bfloat16 ha = __float2bfloat16_rn(a), hb = __float2bfloat16_rn(b);
    __nv_bfloat162 t;
    t.x = __float2bfloat16_rn(a - __bfloat162float(ha));
    t.y = __float2bfloat16_rn(b - __bfloat162float(hb));
    return *reinterpret_cast<uint32_t*>(&t);
}

// ---------------- generic plane GEMM ----------------
// tile 128x128, 8 warps (4m x 2n), k-chunk 32, KPAD=40 rows, double-buffered
constexpr int KPAD   = 40;
constexpr int TILE_B = 128 * KPAD * 2;   // bytes per tile (10240)
constexpr int BUF_B  = 4 * TILE_B;       // bytes per buffer set (40960)
constexpr int SM_BIAS = 2 * BUF_B;       // 81920
constexpr int SM_TOT  = SM_BIAS + 3 * 128 * 4;  // 83456

__device__ __forceinline__ void issue_tile(
    uint32_t sb, int buf, int kt,
    const __nv_bfloat16* A0h, const __nv_bfloat16* A0l, int K0,
    const __nv_bfloat16* A1h, const __nv_bfloat16* A1l, int K1,
    const __nv_bfloat16* Wh, const __nv_bfloat16* Wl, int Kt,
    int mbase, int nbase, int tid)
{
    int kc = kt << 5;
    const __nv_bfloat16 *ah, *al;
    int ld, ko;
    if (kc < K0) { ah = A0h; al = A0l; ld = K0; ko = kc; }
    else         { ah = A1h; al = A1l; ld = K1; ko = kc - K0; }
    uint32_t base = sb + buf * BUF_B;
    #pragma unroll
    for (int r = 0; r < 2; r++) {
        int chunk = tid + r * 256;            // 0..511
        int row = chunk >> 2, c = chunk & 3;
        uint32_t off = row * (KPAD * 2) + c * 16;
        size_t aoff = (size_t)(mbase + row) * ld + ko + c * 8;
        size_t woff = (size_t)(nbase + row) * Kt + kc + c * 8;
        CPA16(base + off,              ah + aoff);
        CPA16(base + TILE_B + off,     al + aoff);
        CPA16(base + 2 * TILE_B + off, Wh + woff);
        CPA16(base + 3 * TILE_B + off, Wl + woff);
    }
}

// mode 0: fp32 out C (+bias), guard gm<M
// mode 1: split planes Dh/Dl (+bias)
// mode 2: AGG epilogue: (acc + ci*b1 + cb*b2 + cc*b3) / max(cnt,1) -> planes
__global__ void __launch_bounds__(256, 2) k_gemm(
    const __nv_bfloat16* __restrict__ A0h, const __nv_bfloat16* __restrict__ A0l, int K0,
    const __nv_bfloat16* __restrict__ A1h, const __nv_bfloat16* __restrict__ A1l, int K1,
    const __nv_bfloat16* __restrict__ Wh,  const __nv_bfloat16* __restrict__ Wl,
    const float* __restrict__ bias,
    float* __restrict__ C, int ldc, int M,
    __nv_bfloat16* __restrict__ Dh, __nv_bfloat16* __restrict__ Dl,
    int mode,
    const float* __restrict__ b1, const float* __restrict__ b2,
    const float* __restrict__ b3)
{
    extern __shared__ char smem[];
    uint32_t sb = cvta_s(smem);
    const int tid  = threadIdx.x;
    const int wid  = tid >> 5;
    const int lane = tid & 31;
    const int wm   = wid >> 1;
    const int wn   = wid & 1;
    const int mbase = blockIdx.x * 128;
    const int nbase = blockIdx.y * 128;
    const int Kt = K0 + K1;
    const int nk = Kt >> 5;

    float* bs1 = (float*)(smem + SM_BIAS);
    float* bs2 = bs1 + 128;
    float* bs3 = bs2 + 128;
    if (tid < 128) {
        if (mode == 2) {
            bs1[tid] = b1[tid]; bs2[tid] = b2[tid]; bs3[tid] = b3[tid];
        } else {
            bs1[tid] = bias ? bias[nbase + tid] : 0.f;
        }
    }

    int jj = lane >> 3;
    uint32_t a_off = (uint32_t)((wm * 32 + (lane & 15)) * (KPAD * 2) + (lane >> 4) * 16);
    uint32_t b_off = (uint32_t)((wn * 64 + ((jj >> 1) * 8) + (lane & 7)) * (KPAD * 2) + (jj & 1) * 16);

    float acc[2][8][4];
    #pragma unroll
    for (int mt = 0; mt < 2; mt++)
        #pragma unroll
        for (int nt = 0; nt < 8; nt++)
            #pragma unroll
            for (int j = 0; j < 4; j++) acc[mt][nt][j] = 0.f;

    issue_tile(sb, 0, 0, A0h, A0l, K0, A1h, A1l, K1, Wh, Wl, Kt, mbase, nbase, tid);
    CPCOMMIT();
    if (nk > 1)
        issue_tile(sb, 1, 1, A0h, A0l, K0, A1h, A1l, K1, Wh, Wl, Kt, mbase, nbase, tid);
    CPCOMMIT();

    for (int kt = 0; kt < nk; kt++) {
        int buf = kt & 1;
        CPWAIT1();
        __syncthreads();
        uint32_t base = sb + buf * BUF_B;
        #pragma unroll
        for (int s = 0; s < 2; s++) {
            uint32_t koff = s * 32;
            uint32_t ah[2][4], al[2][4];
            #pragma unroll
            for (int mt = 0; mt < 2; mt++) {
                uint32_t ad = base + a_off + koff + mt * (16 * KPAD * 2);
                LDSM4(ah[mt][0], ah[mt][1], ah[mt][2], ah[mt][3], ad);
                LDSM4(al[mt][0], al[mt][1], al[mt][2], al[mt][3], ad + TILE_B);
            }
            uint32_t bh[8][2], bl[8][2];
            #pragma unroll
            for (int g = 0; g < 4; g++) {
                uint32_t bd = base + 2 * TILE_B + b_off + koff + g * (16 * KPAD * 2);
                uint32_t r0, r1, r2, r3;
                LDSM4(r0, r1, r2, r3, bd);
                bh[g * 2][0] = r0; bh[g * 2][1] = r1;
                bh[g * 2 + 1][0] = r2; bh[g * 2 + 1][1] = r3;
                LDSM4(r0, r1, r2, r3, bd + TILE_B);
                bl[g * 2][0] = r0; bl[g * 2][1] = r1;
                bl[g * 2 + 1][0] = r2; bl[g * 2 + 1][1] = r3;
            }
            #pragma unroll
            for (int mt = 0; mt < 2; mt++)
                #pragma unroll
                for (int nt = 0; nt < 8; nt++) {
                    MMA16816(acc[mt][nt], ah[mt], bh[nt][0], bh[nt][1]);
                    MMA16816(acc[mt][nt], ah[mt], bl[nt][0], bl[nt][1]);
                    MMA16816(acc[mt][nt], al[mt], bh[nt][0], bh[nt][1]);
                }
        }
        __syncthreads();
        if (kt + 2 < nk)
            issue_tile(sb, buf, kt + 2, A0h, A0l, K0, A1h, A1l, K1, Wh, Wl, Kt,
                       mbase, nbase, tid);
        CPCOMMIT();
    }

    // ---- epilogue ----
    #pragma unroll
    for (int mt = 0; mt < 2; mt++) {
        int r0 = mbase + wm * 32 + mt * 16 + (lane >> 2);
        int r1 = r0 + 8;
        float ci0 = 0.f, cb0 = 0.f, cc0 = 0.f, inv0 = 1.f;
        float ci1 = 0.f, cb1 = 0.f, cc1 = 0.f, inv1 = 1.f;
        if (mode == 2) {
            if (r0 < N_INTn) {
                ci0 = g_cntI[r0]; cb0 = g_cntB[r0]; cc0 = g_cntC[r0];
                inv0 = 1.f / fmaxf(ci0 + cb0 + cc0, 1.f);
            }
            if (r1 < N_INTn) {
                ci1 = g_cntI[r1]; cb1 = g_cntB[r1]; cc1 = g_cntC[r1];
                inv1 = 1.f / fmaxf(ci1 + cb1 + cc1, 1.f);
            }
        }
        #pragma unroll
        for (int nt = 0; nt < 8; nt++) {
            int nl = wn * 64 + nt * 8 + (lane & 3) * 2;
            float v00 = acc[mt][nt][0], v01 = acc[mt][nt][1];
            float v10 = acc[mt][nt][2], v11 = acc[mt][nt][3];
            if (mode == 0) {
                float b0 = bs1[nl], b1v = bs1[nl + 1];
                if (r0 < M) {
                    float2 o = {v00 + b0, v01 + b1v};
                    *reinterpret_cast<float2*>(C + (size_t)r0 * ldc + nbase + nl) = o;
                }
                if (r1 < M) {
                    float2 o = {v10 + b0, v11 + b1v};
                    *reinterpret_cast<float2*>(C + (size_t)r1 * ldc + nbase + nl) = o;
                }
            } else if (mode == 1) {
                float b0 = bs1[nl], b1v = bs1[nl + 1];
                v00 += b0; v01 += b1v; v10 += b0; v11 += b1v;
                size_t i0 = (size_t)r0 * 128 + nbase + nl;
                size_t i1 = (size_t)r1 * 128 + nbase + nl;
                *reinterpret_cast<uint32_t*>(Dh + i0) = pack_bf2(v00, v01);
                *reinterpret_cast<uint32_t*>(Dl + i0) = pack_lo2(v00, v01);
                *reinterpret_cast<uint32_t*>(Dh + i1) = pack_bf2(v10, v11);
                *reinterpret_cast<uint32_t*>(Dl + i1) = pack_lo2(v10, v11);
            } else {
                float e0 = bs1[nl] , e1 = bs1[nl + 1];
                float f0 = bs2[nl] , f1 = bs2[nl + 1];
                float g0 = bs3[nl] , g1 = bs3[nl + 1];
                v00 = (v00 + ci0 * e0 + cb0 * f0 + cc0 * g0) * inv0;
                v01 = (v01 + ci0 * e1 + cb0 * f1 + cc0 * g1) * inv0;
                v10 = (v10 + ci1 * e0 + cb1 * f0 + cc1 * g0) * inv1;
                v11 = (v11 + ci1 * e1 + cb1 * f1 + cc1 * g1) * inv1;
                size_t i0 = (size_t)r0 * 128 + nbase + nl;
                size_t i1 = (size_t)r1 * 128 + nbase + nl;
                *reinterpret_cast<uint32_t*>(Dh + i0) = pack_bf2(v00, v01);
                *reinterpret_cast<uint32_t*>(Dl + i0) = pack_lo2(v00, v01);
                *reinterpret_cast<uint32_t*>(Dh + i1) = pack_bf2(v10, v11);
                *reinterpret_cast<uint32_t*>(Dl + i1) = pack_lo2(v10, v11);
            }
        }
    }
}

// ---------------- zero scratch ----------------
__global__ void k_zero() {
    int idx = blockIdx.x * blockDim.x + threadIdx.x;
    int stride = gridDim.x * blockDim.x;
    float4 z = {0.f, 0.f, 0.f, 0.f};
    float4* f = reinterpret_cast<float4*>(g_feat);
    for (int i = idx; i < N_INTn * 320 / 4; i += stride) f[i] = z;
    for (int i = idx; i < N_INTn; i += stride) {
        g_cntI[i] = 0.f; g_cntB[i] = 0.f; g_cntC[i] = 0.f;
    }
}

// ---------------- fused edge scatter ----------------
__device__ __forceinline__ void red4(float* p, float4 v) {
    asm volatile("red.global.add.v4.f32 [%0], {%1,%2,%3,%4};"
                 :: "l"(p), "f"(v.x), "f"(v.y), "f"(v.z), "f"(v.w) : "memory");
}

constexpr int W_INT = E_INTn / 4;               // 125000
constexpr int W_B   = W_INT + E_Bn / 4;         // 130000
constexpr int W_C   = W_B + E_Cn / 4;           // 132500

__global__ void k_scatter(const int* __restrict__ eiI, const int* __restrict__ eiB,
                          const int* __restrict__ eiC,
                          const float* __restrict__ x, const float* __restrict__ xb,
                          const float* __restrict__ u)
{
    int w = (blockIdx.x * blockDim.x + threadIdx.x) >> 5;
    int lane = threadIdx.x & 31;
    if (w < W_INT) {
        int e0 = w * 4;
        int s[4], t[4];
        #pragma unroll
        for (int j = 0; j < 4; j++) { s[j] = eiI[e0 + j]; t[j] = eiI[E_INTn + e0 + j]; }
        float4 v[4];
        #pragma unroll
        for (int j = 0; j < 4; j++)
            v[j] = ((const float4*)(x + (size_t)s[j] * D))[lane];
        #pragma unroll
        for (int j = 0; j < 4; j++)
            red4(g_feat + (size_t)t[j] * 320 + lane * 4, v[j]);
        if (lane == 0) {
            #pragma unroll
            for (int j = 0; j < 4; j++) atomicAdd(&g_cntI[t[j]], 1.0f);
        }
    } else if (w < W_B) {
        int e0 = (w - W_INT) * 4;
        int t[4];
        #pragma unroll
        for (int j = 0; j < 4; j++) t[j] = eiB[E_Bn + e0 + j];
        float4 v[4];
        #pragma unroll
        for (int j = 0; j < 4; j++)
            v[j] = ((const float4*)(xb + (size_t)(e0 + j) * D))[lane];
        #pragma unroll
        for (int j = 0; j < 4; j++)
            red4(g_feat + (size_t)t[j] * 320 + 128 + lane * 4, v[j]);
        if (lane == 0) {
            #pragma unroll
            for (int j = 0; j < 4; j++) atomicAdd(&g_cntB[t[j]], 1.0f);
        }
    } else if (w < W_C) {
        int e0 = (w - W_B) * 4;
        int t[4];
        #pragma unroll
        for (int j = 0; j < 4; j++) t[j] = eiC[E_Cn + e0 + j];
        if (lane < 16) {
            float4 v[4];
            #pragma unroll
            for (int j = 0; j < 4; j++)
                v[j] = ((const float4*)(u + (size_t)(e0 + j) * DCn))[lane];
            #pragma unroll
            for (int j = 0; j < 4; j++)
                red4(g_feat + (size_t)t[j] * 320 + 256 + lane * 4, v[j]);
        }
        if (lane == 0) {
            #pragma unroll
            for (int j = 0; j < 4; j++) atomicAdd(&g_cntC[t[j]], 1.0f);
        }
    }
}

// ---------------- fused prep: weight planes + biases + A planes + featext ----------------
__device__ __forceinline__ void wsplit(float v, __nv_bfloat16* h, __nv_bfloat16* l, size_t i) {
    __nv_bfloat16 hi = __float2bfloat16_rn(v);
    h[i] = hi;
    l[i] = __float2bfloat16_rn(v - __bfloat162float(hi));
}

constexpr int R_W1  = 128 * KFE;            // 90112
constexpr int R_WOI = R_W1 + 65536;
constexpr int R_WB1 = R_WOI + 16384;
constexpr int R_WOB = R_WB1 + 65536;
constexpr int R_WC1 = R_WOB + 8192;
constexpr int R_WOC = R_WC1 + 49152;
constexpr int R_B1  = R_WOC + 256;
constexpr int R_B2  = R_B1 + 256;
constexpr int R_B3  = R_B2 + 256;          // 295680
constexpr long long R_X  = (long long)R_B3 + (long long)NP_I * 128;
constexpr long long R_XB = R_X + (long long)NP_B * 128;
constexpr long long R_U  = R_XB + (long long)NP_C * 64;
constexpr long long R_FE = R_U + (long long)NP_I * 320;
constexpr long long R_FX = R_FE + (long long)NP_I * 128;   // total

__global__ void k_prep(
    const float* __restrict__ x, const float* __restrict__ xb, const float* __restrict__ u,
    const float* __restrict__ Wii, const float* __restrict__ Wbi, const float* __restrict__ Wci,
    const float* __restrict__ Wbb, const float* __restrict__ Wcc,
    const float* __restrict__ Wis, const float* __restrict__ Wim,
    const float* __restrict__ Wbs, const float* __restrict__ Wbm,
    const float* __restrict__ Wcs, const float* __restrict__ Wcm,
    const float* __restrict__ bis, const float* __restrict__ bim,
    const float* __restrict__ bbs, const float* __restrict__ bbm,
    const float* __restrict__ bcs, const float* __restrict__ bcm)
{
    long long idx = (long long)blockIdx.x * blockDim.x + threadIdx.x;
    if (idx < R_W1) {
        int i = (int)idx;
        int j = i / KFE, k = i % KFE;
        float v;
        if (k < 128)      v = Wii[j * 256 + k];
        else if (k < 256) v = Wbi[j * 256 + (k - 128)];
        else if (k < 320) v = Wci[j * 192 + (k - 256)];
        else if (k < 448) v = Wii[j * 256 + 128 + (k - 320)];
        else if (k < 576) v = Wbi[j * 256 + 128 + (k - 448)];
        else              v = Wci[j * 192 + 64 + (k - 576)];
        wsplit(v, g_W1h, g_W1l, i);
        return;
    }
    if (idx < R_WOI) {
        int i = (int)(idx - R_W1);
        int j = i / 256, k = i % 256;
        float v = (k < 128) ? Wis[j * 128 + k] : Wim[j * 128 + (k - 128)];
        wsplit(v, g_WOIh, g_WOIl, i);
        return;
    }
    if (idx < R_WB1) {
        int i = (int)(idx - R_WOI);
        int j = i / 128, k = i % 128;
        wsplit(Wbb[j * 256 + k] + Wbb[j * 256 + 128 + k], g_WB1h, g_WB1l, i);
        return;
    }
    if (idx < R_WOB) {
        int i = (int)(idx - R_WB1);
        int j = i / 256, k = i % 256;
        float v = (k < 128) ? Wbs[j * 128 + k] : Wbm[j * 128 + (k - 128)];
        wsplit(v, g_WOBh, g_WOBl, i);
        return;
    }
    if (idx < R_WC1) {
        int i = (int)(idx - R_WOB);
        int j = i / 64, k = i % 64;
        wsplit(Wcc[j * 128 + k] + Wcc[j * 128 + 64 + k], g_WC1h, g_WC1l, i);
        return;
    }
    if (idx < R_WOC) {
        int i = (int)(idx - R_WC1);
        int j = i / 192, k = i % 192;
        float v = (k < 64) ? Wcs[j * 64 + k] : Wcm[j * 128 + (k - 64)];
        wsplit(v, g_WOCh, g_WOCl, i);
        return;
    }
    if (idx < R_B1) { int i = (int)(idx - R_WOC); g_bOI[i] = bis[i] + bim[i]; return; }
    if (idx < R_B2) { int i = (int)(idx - R_B1);  g_bOB[i] = bbs[i] + bbm[i]; return; }
    if (idx < R_B3) { int i = (int)(idx - R_B2);  g_bOC[i] = bcs[i] + bcm[i]; return; }
    if (idx < R_X) {
        long long i = idx - R_B3;
        int m = (int)(i >> 7), k = (int)(i & 127);
        float v = (m < N_INTn) ? x[(size_t)m * 128 + k] : 0.f;
        wsplit(v, g_xh, g_xl, (size_t)i);
        return;
    }
    if (idx < R_XB) {
        long long i = idx - R_X;
        int m = (int)(i >> 7), k = (int)(i & 127);
        float v = (m < E_Bn) ? xb[(size_t)m * 128 + k] : 0.f;
        wsplit(v, g_xbh, g_xbl, (size_t)i);
        return;
    }
    if (idx < R_U) {
        long long i = idx - R_XB;
        int m = (int)(i >> 6), k = (int)(i & 63);
        float v = (m < E_Cn) ? u[(size_t)m * 64 + k] : 0.f;
        wsplit(v, g_uh, g_ul, (size_t)i);
        return;
    }
    if (idx < R_FE) {
        long long i = idx - R_U;
        int m = (int)(i / 320), k = (int)(i % 320);
        float v = (m < N_INTn) ? g_feat[(size_t)m * 320 + k] : 0.f;
        wsplit(v, g_feh, g_fel, (size_t)m * KFE + k);
        return;
    }
    if (idx < R_FX) {
        long long i = idx - R_FE;
        int m = (int)(i >> 7), k = (int)(i & 127);
        float xv = 0.f, ci = 0.f, cb = 0.f, cc = 0.f;
        if (m < N_INTn) {
            xv = x[(size_t)m * 128 + k];
            ci = g_cntI[m]; cb = g_cntB[m]; cc = g_cntC[m];
        }
        size_t base = (size_t)m * KFE;
        wsplit(ci * xv, g_feh, g_fel, base + 320 + k);
        wsplit(cb * xv, g_feh, g_fel, base + 448 + k);
        wsplit(cc * xv, g_feh, g_fel, base + 576 + k);
        return;
    }
}

// ---------------- launch ----------------
static void* symv(const void* s) { void* p = nullptr; cudaGetSymbolAddress(&p, s); return p; }

extern "C" void kernel_launch(void* const* d_in, const int* in_sizes, int n_in,
                              void* d_out, int out_size) {
    const float* x   = (const float*)d_in[0];
    const float* xb  = (const float*)d_in[1];
    const float* u   = (const float*)d_in[2];
    const int*   eiI = (const int*)d_in[3];
    const int*   eiB = (const int*)d_in[4];
    const int*   eiC = (const int*)d_in[5];
    const float* Wii = (const float*)d_in[8];
    const float* bii = (const float*)d_in[9];
    const float* Wbi = (const float*)d_in[10];
    const float* bbi = (const float*)d_in[11];
    const float* Wci = (const float*)d_in[12];
    const float* bci = (const float*)d_in[13];
    const float* Wbb = (const float*)d_in[14];
    const float* bbb = (const float*)d_in[15];
    const float* Wcc = (const float*)d_in[16];
    const float* bcc = (const float*)d_in[17];
    const float* Wim = (const float*)d_in[18];
    const float* bim = (const float*)d_in[19];
    const float* Wis = (const float*)d_in[20];
    const float* bis = (const float*)d_in[21];
    const float* Wbm = (const float*)d_in[22];
    const float* bbm = (const float*)d_in[23];
    const float* Wbs = (const float*)d_in[24];
    const float* bbs = (const float*)d_in[25];
    const float* Wcm = (const float*)d_in[26];
    const float* bcm = (const float*)d_in[27];
    const float* Wcs = (const float*)d_in[28];
    const float* bcs = (const float*)d_in[29];
    float* out = (float*)d_out;

    auto bfp = [](const void* s) { return (const __nv_bfloat16*)symv(s); };
    auto bfw = [](const void* s) { return (__nv_bfloat16*)symv(s); };

    const __nv_bfloat16 *pxh = bfp(g_xh), *pxl = bfp(g_xl);
    const __nv_bfloat16 *pxbh = bfp(g_xbh), *pxbl = bfp(g_xbl);
    const __nv_bfloat16 *puh = bfp(g_uh), *pul = bfp(g_ul);
    const __nv_bfloat16 *pfeh = bfp(g_feh), *pfel = bfp(g_fel);
    __nv_bfloat16 *paggh = bfw(g_aggh), *paggl = bfw(g_aggl);
    __nv_bfloat16 *psbh = bfw(g_sbh), *psbl = bfw(g_sbl);
    __nv_bfloat16 *psch = bfw(g_sch), *pscl = bfw(g_scl);
    const __nv_bfloat16 *pW1h = bfp(g_W1h), *pW1l = bfp(g_W1l);
    const __nv_bfloat16 *pWOIh = bfp(g_WOIh), *pWOIl = bfp(g_WOIl);
    const __nv_bfloat16 *pWB1h = bfp(g_WB1h), *pWB1l = bfp(g_WB1l);
    const __nv_bfloat16 *pWOBh = bfp(g_WOBh), *pWOBl = bfp(g_WOBl);
    const __nv_bfloat16 *pWC1h = bfp(g_WC1h), *pWC1l = bfp(g_WC1l);
    const __nv_bfloat16 *pWOCh = bfp(g_WOCh), *pWOCl = bfp(g_WOCl);
    const float *pbOI = (const float*)symv(g_bOI);
    const float *pbOB = (const float*)symv(g_bOB);
    const float *pbOC = (const float*)symv(g_bOC);

    cudaFuncSetAttribute(k_gemm, cudaFuncAttributeMaxDynamicSharedMemorySize, SM_TOT);

    k_zero<<<1024, 256>>>();
    k_scatter<<<(W_C * 32 + 255) / 256, 256>>>(eiI, eiB, eiC, x, xb, u);
    k_prep<<<(int)((R_FX + 255) / 256), 256>>>(
        x, xb, u, Wii, Wbi, Wci, Wbb, Wcc, Wis, Wim, Wbs, Wbm, Wcs, Wcm,
        bis, bim, bbs, bbm, bcs, bcm);

    // AGG = featext @ W1ext^T, epilogue: (+ci*bii+cb*bbi+cc*bci)/cnt -> planes
    k_gemm<<<dim3(391, 1), 256, SM_TOT>>>(
        pfeh, pfel, KFE, nullptr, nullptr, 0, pW1h, pW1l,
        nullptr, nullptr, 0, 0, paggh, paggl, 2, bii, bbi, bci);
    // OUT-I = [x | AGG] @ WOI^T + bOI
    k_gemm<<<dim3(391, 2), 256, SM_TOT>>>(
        pxh, pxl, 128, paggh, paggl, 128, pWOIh, pWOIl,
        pbOI, out, 256, N_INTn, nullptr, nullptr, 0, nullptr, nullptr, nullptr);
    // SB = xb @ WB1^T + bbb -> planes
    k_gemm<<<dim3(157, 1), 256, SM_TOT>>>(
        pxbh, pxbl, 128, nullptr, nullptr, 0, pWB1h, pWB1l,
        bbb, nullptr, 0, 0, psbh, psbl, 1, nullptr, nullptr, nullptr);
    // OUT-B = [xb | SB] @ WOB^T + bOB
    k_gemm<<<dim3(157, 2), 256, SM_TOT>>>(
        pxbh, pxbl, 128, psbh, psbl, 128, pWOBh, pWOBl,
        pbOB, out + (size_t)N_INTn * 256, 256, E_Bn, nullptr, nullptr, 0,
        nullptr, nullptr, nullptr);
    // SC = u @ WC1^T + bcc -> planes
    k_gemm<<<dim3(79, 1), 256, SM_TOT>>>(
        puh, pul, 64, nullptr, nullptr, 0, pWC1h, pWC1l,
        bcc, nullptr, 0, 0, psch, pscl, 1, nullptr, nullptr, nullptr);
    // OUT-C = [u | SC] @ WOC^T + bOC
    k_gemm<<<dim3(79, 2), 256, SM_TOT>>>(
        puh, pul, 64, psch, pscl, 128, pWOCh, pWOCl,
        pbOC, out + (size_t)(N_INTn + E_Bn) * 256, 256, E_Cn, nullptr, nullptr, 0,
        nullptr, nullptr, nullptr);
}

// round 7
// speedup vs baseline: 4.4310x; 1.1105x over previous
#include <cuda_runtime.h>
#include <cuda_bf16.h>
#include <cstdint>
#include <cstddef>

// ---------------- problem constants ----------------
constexpr int N_INTn = 50000;
constexpr int D      = 128;
constexpr int DCn    = 64;
constexpr int E_INTn = 500000;
constexpr int E_Bn   = 20000;
constexpr int E_Cn   = 10000;
constexpr int NP_I   = 50048;   // 391*128
constexpr int NP_B   = 20096;   // 157*128
constexpr int NP_C   = 10112;   // 79*128
constexpr int KFE    = 704;     // featext K

// ---------------- fp32 scratch ----------------
__device__ float g_feat[N_INTn * 320];
__device__ float g_cntI[N_INTn], g_cntB[N_INTn], g_cntC[N_INTn];
__device__ float g_bOI[256], g_bOB[256], g_bOC[256];

// ---------------- bf16 hi/lo planes ----------------
__device__ __align__(16) __nv_bfloat16 g_xh[NP_I * 128],  g_xl[NP_I * 128];
__device__ __align__(16) __nv_bfloat16 g_xbh[NP_B * 128], g_xbl[NP_B * 128];
__device__ __align__(16) __nv_bfloat16 g_uh[NP_C * 64],   g_ul[NP_C * 64];
__device__ __align__(16) __nv_bfloat16 g_feh[(size_t)NP_I * KFE], g_fel[(size_t)NP_I * KFE];
__device__ __align__(16) __nv_bfloat16 g_aggh[NP_I * 128], g_aggl[NP_I * 128];
__device__ __align__(16) __nv_bfloat16 g_sbh[NP_B * 128],  g_sbl[NP_B * 128];
__device__ __align__(16) __nv_bfloat16 g_sch[NP_C * 128],  g_scl[NP_C * 128];
// weight planes
__device__ __align__(16) __nv_bfloat16 g_W1h[128 * KFE], g_W1l[128 * KFE];
__device__ __align__(16) __nv_bfloat16 g_WOIh[256 * 256], g_WOIl[256 * 256];
__device__ __align__(16) __nv_bfloat16 g_WB1h[128 * 128], g_WB1l[128 * 128];
__device__ __align__(16) __nv_bfloat16 g_WOBh[256 * 256], g_WOBl[256 * 256];
__device__ __align__(16) __nv_bfloat16 g_WC1h[128 * 64],  g_WC1l[128 * 64];
__device__ __align__(16) __nv_bfloat16 g_WOCh[256 * 192], g_WOCl[256 * 192];

// ---------------- PTX helpers ----------------
__device__ __forceinline__ uint32_t cvta_s(const void* p) {
    uint32_t a;
    asm("{ .reg .u64 t; cvta.to.shared.u64 t, %1; cvt.u32.u64 %0, t; }" : "=r"(a) : "l"(p));
    return a;
}
#define CPA16(dst, src) asm volatile("cp.async.cg.shared.global [%0], [%1], 16;" :: "r"(dst), "l"(src))
#define CPCOMMIT()      asm volatile("cp.async.commit_group;" ::: "memory")
#define CPWAIT1()       asm volatile("cp.async.wait_group 1;" ::: "memory")

#define LDSM4(r0, r1, r2, r3, a) \
    asm volatile("ldmatrix.sync.aligned.m8n8.x4.shared.b16 {%0,%1,%2,%3}, [%4];" \
                 : "=r"(r0), "=r"(r1), "=r"(r2), "=r"(r3) : "r"(a))

#define MMA16816(c, av, b0, b1) \
    asm volatile("mma.sync.aligned.m16n8k16.row.col.f32.bf16.bf16.f32 " \
                 "{%0,%1,%2,%3}, {%4,%5,%6,%7}, {%8,%9}, {%0,%1,%2,%3};" \
                 : "+f"((c)[0]), "+f"((c)[1]), "+f"((c)[2]), "+f"((c)[3]) \
                 : "r"((av)[0]), "r"((av)[1]), "r"((av)[2]), "r"((av)[3]), \
                   "r"(b0), "r"(b1))

__device__ __forceinline__ uint32_t pack_bf2(float a, float b) {
    __nv_bfloat162 t;
    t.x = __float2bfloat16_rn(a);
    t.y = __float2bfloat16_rn(b);
    return *reinterpret_cast<uint32_t*>(&t);
}
__device__ __forceinline__ uint32_t pack_lo2(float a, float b) {
    __nv_bfloat16 ha = __float2bfloat16_rn(a), hb = __float2bfloat16_rn(b);
    __nv_bfloat162 t;
    t.x = __float2bfloat16_rn(a - __bfloat162float(ha));
    t.y = __float2bfloat16_rn(b - __bfloat162float(hb));
    return *reinterpret_cast<uint32_t*>(&t);
}

// ---------------- generic plane GEMM ----------------
// tile 128x128, 8 warps (4m x 2n), k-chunk 32, swizzled 64B rows, 3-stage pipe
constexpr int TILE_B  = 128 * 64;        // 8192 bytes per plane tile
constexpr int STAGE_B = 4 * TILE_B;      // 32768 bytes per stage (ah,al,wh,wl)
constexpr int SM_BIAS = 3 * STAGE_B;     // 98304
constexpr int SM_TOT  = SM_BIAS + 3 * 128 * 4;  // 99840

__device__ __forceinline__ void issue_tile(
    uint32_t sb, int stage, int kt,
    const __nv_bfloat16* A0h, const __nv_bfloat16* A0l, int K0,
    const __nv_bfloat16* A1h, const __nv_bfloat16* A1l, int K1,
    const __nv_bfloat16* Wh, const __nv_bfloat16* Wl, int Kt,
    int mbase, int nbase, int tid)
{
    int kc = kt << 5;
    const __nv_bfloat16 *ah, *al;
    int ld, ko;
    if (kc < K0) { ah = A0h; al = A0l; ld = K0; ko = kc; }
    else         { ah = A1h; al = A1l; ld = K1; ko = kc - K0; }
    uint32_t base = sb + stage * STAGE_B;
    #pragma unroll
    for (int r = 0; r < 2; r++) {
        int chunk = tid + r * 256;            // 0..511
        int row = chunk >> 2, c = chunk & 3;
        uint32_t sc = (uint32_t)(c ^ ((row >> 1) & 3));
        uint32_t off = row * 64 + sc * 16;
        size_t aoff = (size_t)(mbase + row) * ld + ko + c * 8;
        size_t woff = (size_t)(nbase + row) * Kt + kc + c * 8;
        CPA16(base + off,              ah + aoff);
        CPA16(base + TILE_B + off,     al + aoff);
        CPA16(base + 2 * TILE_B + off, Wh + woff);
        CPA16(base + 3 * TILE_B + off, Wl + woff);
    }
}

// mode 0: fp32 out C (+bias), guard gm<M
// mode 1: split planes Dh/Dl (+bias)
// mode 2: AGG epilogue: (acc + ci*b1 + cb*b2 + cc*b3) / max(cnt,1) -> planes
__global__ void __launch_bounds__(256, 2) k_gemm(
    const __nv_bfloat16* __restrict__ A0h, const __nv_bfloat16* __restrict__ A0l, int K0,
    const __nv_bfloat16* __restrict__ A1h, const __nv_bfloat16* __restrict__ A1l, int K1,
    const __nv_bfloat16* __restrict__ Wh,  const __nv_bfloat16* __restrict__ Wl,
    const float* __restrict__ bias,
    float* __restrict__ C, int ldc, int M,
    __nv_bfloat16* __restrict__ Dh, __nv_bfloat16* __restrict__ Dl,
    int mode,
    const float* __restrict__ b1, const float* __restrict__ b2,
    const float* __restrict__ b3)
{
    extern __shared__ char smem[];
    uint32_t sb = cvta_s(smem);
    const int tid  = threadIdx.x;
    const int wid  = tid >> 5;
    const int lane = tid & 31;
    const int wm   = wid >> 1;
    const int wn   = wid & 1;
    const int mbase = blockIdx.x * 128;
    const int nbase = blockIdx.y * 128;
    const int Kt = K0 + K1;
    const int nk = Kt >> 5;

    float* bs1 = (float*)(smem + SM_BIAS);
    float* bs2 = bs1 + 128;
    float* bs3 = bs2 + 128;
    if (tid < 128) {
        if (mode == 2) {
            bs1[tid] = b1[tid]; bs2[tid] = b2[tid]; bs3[tid] = b3[tid];
        } else {
            bs1[tid] = bias ? bias[nbase + tid] : 0.f;
        }
    }

    // ldmatrix lane geometry (swizzled 64B rows)
    const int hi = lane >> 4;                 // A col-half select
    const int jj = lane >> 3;                 // B quadrant select
    const int a_row0 = wm * 32 + (lane & 15); // rows for mt=0 (mt*16 keeps xr)
    const uint32_t xr_a = (uint32_t)((a_row0 >> 1) & 3);
    const uint32_t a_ro[2] = {(uint32_t)(a_row0 * 64), (uint32_t)((a_row0 + 16) * 64)};
    const int b_row0 = wn * 64 + ((jj >> 1) * 8) + (lane & 7);
    const uint32_t xr_b = (uint32_t)((b_row0 >> 1) & 3);
    const uint32_t b_ro = (uint32_t)(b_row0 * 64);
    const uint32_t b_ch = (uint32_t)(jj & 1);

    float acc[2][8][4];
    #pragma unroll
    for (int mt = 0; mt < 2; mt++)
        #pragma unroll
        for (int nt = 0; nt < 8; nt++)
            #pragma unroll
            for (int j = 0; j < 4; j++) acc[mt][nt][j] = 0.f;

    issue_tile(sb, 0, 0, A0h, A0l, K0, A1h, A1l, K1, Wh, Wl, Kt, mbase, nbase, tid);
    CPCOMMIT();
    if (nk > 1)
        issue_tile(sb, 1, 1, A0h, A0l, K0, A1h, A1l, K1, Wh, Wl, Kt, mbase, nbase, tid);
    CPCOMMIT();

    for (int kt = 0; kt < nk; kt++) {
        int stage = kt % 3;
        CPWAIT1();
        __syncthreads();
        uint32_t base = sb + stage * STAGE_B;
        #pragma unroll
        for (int s = 0; s < 2; s++) {
            uint32_t ca = ((uint32_t)(s * 2 + hi) ^ xr_a) * 16;
            uint32_t cb = ((uint32_t)(s * 2) + b_ch ^ xr_b) * 16;
            uint32_t ah[2][4], al[2][4];
            #pragma unroll
            for (int mt = 0; mt < 2; mt++) {
                uint32_t ad = base + a_ro[mt] + ca;
                LDSM4(ah[mt][0], ah[mt][1], ah[mt][2], ah[mt][3], ad);
                LDSM4(al[mt][0], al[mt][1], al[mt][2], al[mt][3], ad + TILE_B);
            }
            uint32_t bh[8][2], bl[8][2];
            #pragma unroll
            for (int g = 0; g < 4; g++) {
                uint32_t bd = base + 2 * TILE_B + b_ro + g * 1024 + cb;
                uint32_t r0, r1, r2, r3;
                LDSM4(r0, r1, r2, r3, bd);
                bh[g * 2][0] = r0; bh[g * 2][1] = r1;
                bh[g * 2 + 1][0] = r2; bh[g * 2 + 1][1] = r3;
                LDSM4(r0, r1, r2, r3, bd + TILE_B);
                bl[g * 2][0] = r0; bl[g * 2][1] = r1;
                bl[g * 2 + 1][0] = r2; bl[g * 2 + 1][1] = r3;
            }
            #pragma unroll
            for (int mt = 0; mt < 2; mt++)
                #pragma unroll
                for (int nt = 0; nt < 8; nt++) {
                    MMA16816(acc[mt][nt], ah[mt], bh[nt][0], bh[nt][1]);
                    MMA16816(acc[mt][nt], ah[mt], bl[nt][0], bl[nt][1]);
                    MMA16816(acc[mt][nt], al[mt], bh[nt][0], bh[nt][1]);
                }
        }
        if (kt + 2 < nk)
            issue_tile(sb, (kt + 2) % 3, kt + 2, A0h, A0l, K0, A1h, A1l, K1,
                       Wh, Wl, Kt, mbase, nbase, tid);
        CPCOMMIT();
    }

    // ---- epilogue ----
    #pragma unroll
    for (int mt = 0; mt < 2; mt++) {
        int r0 = mbase + wm * 32 + mt * 16 + (lane >> 2);
        int r1 = r0 + 8;
        float ci0 = 0.f, cb0 = 0.f, cc0 = 0.f, inv0 = 1.f;
        float ci1 = 0.f, cb1 = 0.f, cc1 = 0.f, inv1 = 1.f;
        if (mode == 2) {
            if (r0 < N_INTn) {
                ci0 = g_cntI[r0]; cb0 = g_cntB[r0]; cc0 = g_cntC[r0];
                inv0 = 1.f / fmaxf(ci0 + cb0 + cc0, 1.f);
            }
            if (r1 < N_INTn) {
                ci1 = g_cntI[r1]; cb1 = g_cntB[r1]; cc1 = g_cntC[r1];
                inv1 = 1.f / fmaxf(ci1 + cb1 + cc1, 1.f);
            }
        }
        #pragma unroll
        for (int nt = 0; nt < 8; nt++) {
            int nl = wn * 64 + nt * 8 + (lane & 3) * 2;
            float v00 = acc[mt][nt][0], v01 = acc[mt][nt][1];
            float v10 = acc[mt][nt][2], v11 = acc[mt][nt][3];
            if (mode == 0) {
                float b0 = bs1[nl], b1v = bs1[nl + 1];
                if (r0 < M) {
                    float2 o = {v00 + b0, v01 + b1v};
                    *reinterpret_cast<float2*>(C + (size_t)r0 * ldc + nbase + nl) = o;
                }
                if (r1 < M) {
                    float2 o = {v10 + b0, v11 + b1v};
                    *reinterpret_cast<float2*>(C + (size_t)r1 * ldc + nbase + nl) = o;
                }
            } else if (mode == 1) {
                float b0 = bs1[nl], b1v = bs1[nl + 1];
                v00 += b0; v01 += b1v; v10 += b0; v11 += b1v;
                size_t i0 = (size_t)r0 * 128 + nbase + nl;
                size_t i1 = (size_t)r1 * 128 + nbase + nl;
                *reinterpret_cast<uint32_t*>(Dh + i0) = pack_bf2(v00, v01);
                *reinterpret_cast<uint32_t*>(Dl + i0) = pack_lo2(v00, v01);
                *reinterpret_cast<uint32_t*>(Dh + i1) = pack_bf2(v10, v11);
                *reinterpret_cast<uint32_t*>(Dl + i1) = pack_lo2(v10, v11);
            } else {
                float e0 = bs1[nl] , e1 = bs1[nl + 1];
                float f0 = bs2[nl] , f1 = bs2[nl + 1];
                float g0 = bs3[nl] , g1 = bs3[nl + 1];
                v00 = (v00 + ci0 * e0 + cb0 * f0 + cc0 * g0) * inv0;
                v01 = (v01 + ci0 * e1 + cb0 * f1 + cc0 * g1) * inv0;
                v10 = (v10 + ci1 * e0 + cb1 * f0 + cc1 * g0) * inv1;
                v11 = (v11 + ci1 * e1 + cb1 * f1 + cc1 * g1) * inv1;
                size_t i0 = (size_t)r0 * 128 + nbase + nl;
                size_t i1 = (size_t)r1 * 128 + nbase + nl;
                *reinterpret_cast<uint32_t*>(Dh + i0) = pack_bf2(v00, v01);
                *reinterpret_cast<uint32_t*>(Dl + i0) = pack_lo2(v00, v01);
                *reinterpret_cast<uint32_t*>(Dh + i1) = pack_bf2(v10, v11);
                *reinterpret_cast<uint32_t*>(Dl + i1) = pack_lo2(v10, v11);
            }
        }
    }
}

// ---------------- zero scratch ----------------
__global__ void k_zero() {
    int idx = blockIdx.x * blockDim.x + threadIdx.x;
    int stride = gridDim.x * blockDim.x;
    float4 z = {0.f, 0.f, 0.f, 0.f};
    float4* f = reinterpret_cast<float4*>(g_feat);
    for (int i = idx; i < N_INTn * 320 / 4; i += stride) f[i] = z;
    for (int i = idx; i < N_INTn; i += stride) {
        g_cntI[i] = 0.f; g_cntB[i] = 0.f; g_cntC[i] = 0.f;
    }
}

// ---------------- fused edge scatter ----------------
__device__ __forceinline__ void red4(float* p, float4 v) {
    asm volatile("red.global.add.v4.f32 [%0], {%1,%2,%3,%4};"
                 :: "l"(p), "f"(v.x), "f"(v.y), "f"(v.z), "f"(v.w) : "memory");
}

constexpr int W_INT = E_INTn / 4;               // 125000
constexpr int W_B   = W_INT + E_Bn / 4;         // 130000
constexpr int W_C   = W_B + E_Cn / 4;           // 132500

__global__ void k_scatter(const int* __restrict__ eiI, const int* __restrict__ eiB,
                          const int* __restrict__ eiC,
                          const float* __restrict__ x, const float* __restrict__ xb,
                          const float* __restrict__ u)
{
    int w = (blockIdx.x * blockDim.x + threadIdx.x) >> 5;
    int lane = threadIdx.x & 31;
    if (w < W_INT) {
        int e0 = w * 4;
        int s[4], t[4];
        #pragma unroll
        for (int j = 0; j < 4; j++) { s[j] = eiI[e0 + j]; t[j] = eiI[E_INTn + e0 + j]; }
        float4 v[4];
        #pragma unroll
        for (int j = 0; j < 4; j++)
            v[j] = ((const float4*)(x + (size_t)s[j] * D))[lane];
        #pragma unroll
        for (int j = 0; j < 4; j++)
            red4(g_feat + (size_t)t[j] * 320 + lane * 4, v[j]);
        if (lane == 0) {
            #pragma unroll
            for (int j = 0; j < 4; j++) atomicAdd(&g_cntI[t[j]], 1.0f);
        }
    } else if (w < W_B) {
        int e0 = (w - W_INT) * 4;
        int t[4];
        #pragma unroll
        for (int j = 0; j < 4; j++) t[j] = eiB[E_Bn + e0 + j];
        float4 v[4];
        #pragma unroll
        for (int j = 0; j < 4; j++)
            v[j] = ((const float4*)(xb + (size_t)(e0 + j) * D))[lane];
        #pragma unroll
        for (int j = 0; j < 4; j++)
            red4(g_feat + (size_t)t[j] * 320 + 128 + lane * 4, v[j]);
        if (lane == 0) {
            #pragma unroll
            for (int j = 0; j < 4; j++) atomicAdd(&g_cntB[t[j]], 1.0f);
        }
    } else if (w < W_C) {
        int e0 = (w - W_B) * 4;
        int t[4];
        #pragma unroll
        for (int j = 0; j < 4; j++) t[j] = eiC[E_Cn + e0 + j];
        if (lane < 16) {
            float4 v[4];
            #pragma unroll
            for (int j = 0; j < 4; j++)
                v[j] = ((const float4*)(u + (size_t)(e0 + j) * DCn))[lane];
            #pragma unroll
            for (int j = 0; j < 4; j++)
                red4(g_feat + (size_t)t[j] * 320 + 256 + lane * 4, v[j]);
        }
        if (lane == 0) {
            #pragma unroll
            for (int j = 0; j < 4; j++) atomicAdd(&g_cntC[t[j]], 1.0f);
        }
    }
}

// ---------------- fused prep: weight planes + biases + A planes + featext ----------------
__device__ __forceinline__ void wsplit(float v, __nv_bfloat16* h, __nv_bfloat16* l, size_t i) {
    __nv_bfloat16 hi = __float2bfloat16_rn(v);
    h[i] = hi;
    l[i] = __float2bfloat16_rn(v - __bfloat162float(hi));
}

constexpr int R_W1  = 128 * KFE;            // 90112
constexpr int R_WOI = R_W1 + 65536;
constexpr int R_WB1 = R_WOI + 16384;
constexpr int R_WOB = R_WB1 + 65536;
constexpr int R_WC1 = R_WOB + 8192;
constexpr int R_WOC = R_WC1 + 49152;
constexpr int R_B1  = R_WOC + 256;
constexpr int R_B2  = R_B1 + 256;
constexpr int R_B3  = R_B2 + 256;          // 295680
constexpr long long R_X  = (long long)R_B3 + (long long)NP_I * 128;
constexpr long long R_XB = R_X + (long long)NP_B * 128;
constexpr long long R_U  = R_XB + (long long)NP_C * 64;
constexpr long long R_FE = R_U + (long long)NP_I * 320;
constexpr long long R_FX = R_FE + (long long)NP_I * 128;   // total

__global__ void k_prep(
    const float* __restrict__ x, const float* __restrict__ xb, const float* __restrict__ u,
    const float* __restrict__ Wii, const float* __restrict__ Wbi, const float* __restrict__ Wci,
    const float* __restrict__ Wbb, const float* __restrict__ Wcc,
    const float* __restrict__ Wis, const float* __restrict__ Wim,
    const float* __restrict__ Wbs, const float* __restrict__ Wbm,
    const float* __restrict__ Wcs, const float* __restrict__ Wcm,
    const float* __restrict__ bis, const float* __restrict__ bim,
    const float* __restrict__ bbs, const float* __restrict__ bbm,
    const float* __restrict__ bcs, const float* __restrict__ bcm)
{
    long long idx = (long long)blockIdx.x * blockDim.x + threadIdx.x;
    if (idx < R_W1) {
        int i = (int)idx;
        int j = i / KFE, k = i % KFE;
        float v;
        if (k < 128)      v = Wii[j * 256 + k];
        else if (k < 256) v = Wbi[j * 256 + (k - 128)];
        else if (k < 320) v = Wci[j * 192 + (k - 256)];
        else if (k < 448) v = Wii[j * 256 + 128 + (k - 320)];
        else if (k < 576) v = Wbi[j * 256 + 128 + (k - 448)];
        else              v = Wci[j * 192 + 64 + (k - 576)];
        wsplit(v, g_W1h, g_W1l, i);
        return;
    }
    if (idx < R_WOI) {
        int i = (int)(idx - R_W1);
        int j = i / 256, k = i % 256;
        float v = (k < 128) ? Wis[j * 128 + k] : Wim[j * 128 + (k - 128)];
        wsplit(v, g_WOIh, g_WOIl, i);
        return;
    }
    if (idx < R_WB1) {
        int i = (int)(idx - R_WOI);
        int j = i / 128, k = i % 128;
        wsplit(Wbb[j * 256 + k] + Wbb[j * 256 + 128 + k], g_WB1h, g_WB1l, i);
        return;
    }
    if (idx < R_WOB) {
        int i = (int)(idx - R_WB1);
        int j = i / 256, k = i % 256;
        float v = (k < 128) ? Wbs[j * 128 + k] : Wbm[j * 128 + (k - 128)];
        wsplit(v, g_WOBh, g_WOBl, i);
        return;
    }
    if (idx < R_WC1) {
        int i = (int)(idx - R_WOB);
        int j = i / 64, k = i % 64;
        wsplit(Wcc[j * 128 + k] + Wcc[j * 128 + 64 + k], g_WC1h, g_WC1l, i);
        return;
    }
    if (idx < R_WOC) {
        int i = (int)(idx - R_WC1);
        int j = i / 192, k = i % 192;
        float v = (k < 64) ? Wcs[j * 64 + k] : Wcm[j * 128 + (k - 64)];
        wsplit(v, g_WOCh, g_WOCl, i);
        return;
    }
    if (idx < R_B1) { int i = (int)(idx - R_WOC); g_bOI[i] = bis[i] + bim[i]; return; }
    if (idx < R_B2) { int i = (int)(idx - R_B1);  g_bOB[i] = bbs[i] + bbm[i]; return; }
    if (idx < R_B3) { int i = (int)(idx - R_B2);  g_bOC[i] = bcs[i] + bcm[i]; return; }
    if (idx < R_X) {
        long long i = idx - R_B3;
        int m = (int)(i >> 7), k = (int)(i & 127);
        float v = (m < N_INTn) ? x[(size_t)m * 128 + k] : 0.f;
        wsplit(v, g_xh, g_xl, (size_t)i);
        return;
    }
    if (idx < R_XB) {
        long long i = idx - R_X;
        int m = (int)(i >> 7), k = (int)(i & 127);
        float v = (m < E_Bn) ? xb[(size_t)m * 128 + k] : 0.f;
        wsplit(v, g_xbh, g_xbl, (size_t)i);
        return;
    }
    if (idx < R_U) {
        long long i = idx - R_XB;
        int m = (int)(i >> 6), k = (int)(i & 63);
        float v = (m < E_Cn) ? u[(size_t)m * 64 + k] : 0.f;
        wsplit(v, g_uh, g_ul, (size_t)i);
        return;
    }
    if (idx < R_FE) {
        long long i = idx - R_U;
        int m = (int)(i / 320), k = (int)(i % 320);
        float v = (m < N_INTn) ? g_feat[(size_t)m * 320 + k] : 0.f;
        wsplit(v, g_feh, g_fel, (size_t)m * KFE + k);
        return;
    }
    if (idx < R_FX) {
        long long i = idx - R_FE;
        int m = (int)(i >> 7), k = (int)(i & 127);
        float xv = 0.f, ci = 0.f, cb = 0.f, cc = 0.f;
        if (m < N_INTn) {
            xv = x[(size_t)m * 128 + k];
            ci = g_cntI[m]; cb = g_cntB[m]; cc = g_cntC[m];
        }
        size_t base = (size_t)m * KFE;
        wsplit(ci * xv, g_feh, g_fel, base + 320 + k);
        wsplit(cb * xv, g_feh, g_fel, base + 448 + k);
        wsplit(cc * xv, g_feh, g_fel, base + 576 + k);
        return;
    }
}

// ---------------- launch ----------------
static void* symv(const void* s) { void* p = nullptr; cudaGetSymbolAddress(&p, s); return p; }

extern "C" void kernel_launch(void* const* d_in, const int* in_sizes, int n_in,
                              void* d_out, int out_size) {
    const float* x   = (const float*)d_in[0];
    const float* xb  = (const float*)d_in[1];
    const float* u   = (const float*)d_in[2];
    const int*   eiI = (const int*)d_in[3];
    const int*   eiB = (const int*)d_in[4];
    const int*   eiC = (const int*)d_in[5];
    const float* Wii = (const float*)d_in[8];
    const float* bii = (const float*)d_in[9];
    const float* Wbi = (const float*)d_in[10];
    const float* bbi = (const float*)d_in[11];
    const float* Wci = (const float*)d_in[12];
    const float* bci = (const float*)d_in[13];
    const float* Wbb = (const float*)d_in[14];
    const float* bbb = (const float*)d_in[15];
    const float* Wcc = (const float*)d_in[16];
    const float* bcc = (const float*)d_in[17];
    const float* Wim = (const float*)d_in[18];
    const float* bim = (const float*)d_in[19];
    const float* Wis = (const float*)d_in[20];
    const float* bis = (const float*)d_in[21];
    const float* Wbm = (const float*)d_in[22];
    const float* bbm = (const float*)d_in[23];
    const float* Wbs = (const float*)d_in[24];
    const float* bbs = (const float*)d_in[25];
    const float* Wcm = (const float*)d_in[26];
    const float* bcm = (const float*)d_in[27];
    const float* Wcs = (const float*)d_in[28];
    const float* bcs = (const float*)d_in[29];
    float* out = (float*)d_out;

    auto bfp = [](const void* s) { return (const __nv_bfloat16*)symv(s); };
    auto bfw = [](const void* s) { return (__nv_bfloat16*)symv(s); };

    const __nv_bfloat16 *pxh = bfp(g_xh), *pxl = bfp(g_xl);
    const __nv_bfloat16 *pxbh = bfp(g_xbh), *pxbl = bfp(g_xbl);
    const __nv_bfloat16 *puh = bfp(g_uh), *pul = bfp(g_ul);
    const __nv_bfloat16 *pfeh = bfp(g_feh), *pfel = bfp(g_fel);
    __nv_bfloat16 *paggh = bfw(g_aggh), *paggl = bfw(g_aggl);
    __nv_bfloat16 *psbh = bfw(g_sbh), *psbl = bfw(g_sbl);
    __nv_bfloat16 *psch = bfw(g_sch), *pscl = bfw(g_scl);
    const __nv_bfloat16 *pW1h = bfp(g_W1h), *pW1l = bfp(g_W1l);
    const __nv_bfloat16 *pWOIh = bfp(g_WOIh), *pWOIl = bfp(g_WOIl);
    const __nv_bfloat16 *pWB1h = bfp(g_WB1h), *pWB1l = bfp(g_WB1l);
    const __nv_bfloat16 *pWOBh = bfp(g_WOBh), *pWOBl = bfp(g_WOBl);
    const __nv_bfloat16 *pWC1h = bfp(g_WC1h), *pWC1l = bfp(g_WC1l);
    const __nv_bfloat16 *pWOCh = bfp(g_WOCh), *pWOCl = bfp(g_WOCl);
    const float *pbOI = (const float*)symv(g_bOI);
    const float *pbOB = (const float*)symv(g_bOB);
    const float *pbOC = (const float*)symv(g_bOC);

    cudaFuncSetAttribute(k_gemm, cudaFuncAttributeMaxDynamicSharedMemorySize, SM_TOT);

    k_zero<<<1024, 256>>>();
    k_scatter<<<(W_C * 32 + 255) / 256, 256>>>(eiI, eiB, eiC, x, xb, u);
    k_prep<<<(int)((R_FX + 255) / 256), 256>>>(
        x, xb, u, Wii, Wbi, Wci, Wbb, Wcc, Wis, Wim, Wbs, Wbm, Wcs, Wcm,
        bis, bim, bbs, bbm, bcs, bcm);

    // AGG = featext @ W1ext^T, epilogue: (+ci*bii+cb*bbi+cc*bci)/cnt -> planes
    k_gemm<<<dim3(391, 1), 256, SM_TOT>>>(
        pfeh, pfel, KFE, nullptr, nullptr, 0, pW1h, pW1l,
        nullptr, nullptr, 0, 0, paggh, paggl, 2, bii, bbi, bci);
    // OUT-I = [x | AGG] @ WOI^T + bOI
    k_gemm<<<dim3(391, 2), 256, SM_TOT>>>(
        pxh, pxl, 128, paggh, paggl, 128, pWOIh, pWOIl,
        pbOI, out, 256, N_INTn, nullptr, nullptr, 0, nullptr, nullptr, nullptr);
    // SB = xb @ WB1^T + bbb -> planes
    k_gemm<<<dim3(157, 1), 256, SM_TOT>>>(
        pxbh, pxbl, 128, nullptr, nullptr, 0, pWB1h, pWB1l,
        bbb, nullptr, 0, 0, psbh, psbl, 1, nullptr, nullptr, nullptr);
    // OUT-B = [xb | SB] @ WOB^T + bOB
    k_gemm<<<dim3(157, 2), 256, SM_TOT>>>(
        pxbh, pxbl, 128, psbh, psbl, 128, pWOBh, pWOBl,
        pbOB, out + (size_t)N_INTn * 256, 256, E_Bn, nullptr, nullptr, 0,
        nullptr, nullptr, nullptr);
    // SC = u @ WC1^T + bcc -> planes
    k_gemm<<<dim3(79, 1), 256, SM_TOT>>>(
        puh, pul, 64, nullptr, nullptr, 0, pWC1h, pWC1l,
        bcc, nullptr, 0, 0, psch, pscl, 1, nullptr, nullptr, nullptr);
    // OUT-C = [u | SC] @ WOC^T + bOC
    k_gemm<<<dim3(79, 2), 256, SM_TOT>>>(
        puh, pul, 64, psch, pscl, 128, pWOCh, pWOCl,
        pbOC, out + (size_t)(N_INTn + E_Bn) * 256, 256, E_Cn, nullptr, nullptr, 0,
        nullptr, nullptr, nullptr);
}

// round 8
// speedup vs baseline: 5.1707x; 1.1669x over previous
#include <cuda_runtime.h>
#include <cuda_bf16.h>
#include <cstdint>
#include <cstddef>

// ---------------- problem constants ----------------
constexpr int N_INTn = 50000;
constexpr int D      = 128;
constexpr int DCn    = 64;
constexpr int E_INTn = 500000;
constexpr int E_Bn   = 20000;
constexpr int E_Cn   = 10000;
constexpr int NP_I   = 50048;   // 391*128
constexpr int NP_B   = 20096;   // 157*128
constexpr int NP_C   = 10112;   // 79*128
constexpr int KFE    = 704;     // featext K

// ---------------- fp32 scratch ----------------
__device__ float g_feat[N_INTn * 320];
__device__ float g_cntI[N_INTn], g_cntB[N_INTn], g_cntC[N_INTn];
__device__ float g_bOI[256], g_bOB[256], g_bOC[256];

// ---------------- bf16 hi/lo planes ----------------
__device__ __align__(16) __nv_bfloat16 g_xh[NP_I * 128],  g_xl[NP_I * 128];
__device__ __align__(16) __nv_bfloat16 g_xbh[NP_B * 128], g_xbl[NP_B * 128];
__device__ __align__(16) __nv_bfloat16 g_uh[NP_C * 64],   g_ul[NP_C * 64];
__device__ __align__(16) __nv_bfloat16 g_feh[(size_t)NP_I * KFE], g_fel[(size_t)NP_I * KFE];
__device__ __align__(16) __nv_bfloat16 g_aggh[NP_I * 128], g_aggl[NP_I * 128];
__device__ __align__(16) __nv_bfloat16 g_sbh[NP_B * 128],  g_sbl[NP_B * 128];
__device__ __align__(16) __nv_bfloat16 g_sch[NP_C * 128],  g_scl[NP_C * 128];
// weight planes
__device__ __align__(16) __nv_bfloat16 g_W1h[128 * KFE], g_W1l[128 * KFE];
__device__ __align__(16) __nv_bfloat16 g_WOIh[256 * 256], g_WOIl[256 * 256];
__device__ __align__(16) __nv_bfloat16 g_WB1h[128 * 128], g_WB1l[128 * 128];
__device__ __align__(16) __nv_bfloat16 g_WOBh[256 * 256], g_WOBl[256 * 256];
__device__ __align__(16) __nv_bfloat16 g_WC1h[128 * 64],  g_WC1l[128 * 64];
__device__ __align__(16) __nv_bfloat16 g_WOCh[256 * 192], g_WOCl[256 * 192];

// ---------------- PTX helpers ----------------
__device__ __forceinline__ uint32_t cvta_s(const void* p) {
    uint32_t a;
    asm("{ .reg .u64 t; cvta.to.shared.u64 t, %1; cvt.u32.u64 %0, t; }" : "=r"(a) : "l"(p));
    return a;
}
#define CPA16(dst, src) asm volatile("cp.async.cg.shared.global [%0], [%1], 16;" :: "r"(dst), "l"(src))
#define CPCOMMIT()      asm volatile("cp.async.commit_group;" ::: "memory")
#define CPWAIT1()       asm volatile("cp.async.wait_group 1;" ::: "memory")

#define LDSM4(r0, r1, r2, r3, a) \
    asm volatile("ldmatrix.sync.aligned.m8n8.x4.shared.b16 {%0,%1,%2,%3}, [%4];" \
                 : "=r"(r0), "=r"(r1), "=r"(r2), "=r"(r3) : "r"(a))

#define MMA16816(c, av, b0, b1) \
    asm volatile("mma.sync.aligned.m16n8k16.row.col.f32.bf16.bf16.f32 " \
                 "{%0,%1,%2,%3}, {%4,%5,%6,%7}, {%8,%9}, {%0,%1,%2,%3};" \
                 : "+f"((c)[0]), "+f"((c)[1]), "+f"((c)[2]), "+f"((c)[3]) \
                 : "r"((av)[0]), "r"((av)[1]), "r"((av)[2]), "r"((av)[3]), \
                   "r"(b0), "r"(b1))

__device__ __forceinline__ uint32_t pack_bf2(float a, float b) {
    __nv_bfloat162 t;
    t.x = __float2bfloat16_rn(a);
    t.y = __float2bfloat16_rn(b);
    return *reinterpret_cast<uint32_t*>(&t);
}
__device__ __forceinline__ uint32_t pack_lo2(float a, float b) {
    __nv_bfloat16 ha = __float2bfloat16_rn(a), hb = __float2bfloat16_rn(b);
    __nv_bfloat162 t;
    t.x = __float2bfloat16_rn(a - __bfloat162float(ha));
    t.y = __float2bfloat16_rn(b - __bfloat162float(hb));
    return *reinterpret_cast<uint32_t*>(&t);
}

// ---------------- generic plane GEMM ----------------
// tile 128x128, 8 warps (4m x 2n), k-chunk 32, swizzled 64B rows, 3-stage pipe
constexpr int TILE_B  = 128 * 64;        // 8192 bytes per plane tile
constexpr int STAGE_B = 4 * TILE_B;      // 32768 bytes per stage (ah,al,wh,wl)
constexpr int SM_BIAS = 3 * STAGE_B;     // 98304
constexpr int SM_TOT  = SM_BIAS + 3 * 128 * 4;  // 99840

__device__ __forceinline__ void issue_tile(
    uint32_t sb, int stage, int kt,
    const __nv_bfloat16* A0h, const __nv_bfloat16* A0l, int K0,
    const __nv_bfloat16* A1h, const __nv_bfloat16* A1l, int K1,
    const __nv_bfloat16* Wh, const __nv_bfloat16* Wl, int Kt,
    int mbase, int nbase, int tid)
{
    int kc = kt << 5;
    const __nv_bfloat16 *ah, *al;
    int ld, ko;
    if (kc < K0) { ah = A0h; al = A0l; ld = K0; ko = kc; }
    else         { ah = A1h; al = A1l; ld = K1; ko = kc - K0; }
    uint32_t base = sb + stage * STAGE_B;
    #pragma unroll
    for (int r = 0; r < 2; r++) {
        int chunk = tid + r * 256;            // 0..511
        int row = chunk >> 2, c = chunk & 3;
        uint32_t sc = (uint32_t)(c ^ ((row >> 1) & 3));
        uint32_t off = row * 64 + sc * 16;
        size_t aoff = (size_t)(mbase + row) * ld + ko + c * 8;
        size_t woff = (size_t)(nbase + row) * Kt + kc + c * 8;
        CPA16(base + off,              ah + aoff);
        CPA16(base + TILE_B + off,     al + aoff);
        CPA16(base + 2 * TILE_B + off, Wh + woff);
        CPA16(base + 3 * TILE_B + off, Wl + woff);
    }
}

// mode 0: fp32 out C (+bias), guard gm<M
// mode 1: split planes Dh/Dl (+bias)
// mode 2: AGG epilogue: (acc + ci*b1 + cb*b2 + cc*b3) / max(cnt,1) -> planes
__global__ void __launch_bounds__(256, 2) k_gemm(
    const __nv_bfloat16* __restrict__ A0h, const __nv_bfloat16* __restrict__ A0l, int K0,
    const __nv_bfloat16* __restrict__ A1h, const __nv_bfloat16* __restrict__ A1l, int K1,
    const __nv_bfloat16* __restrict__ Wh,  const __nv_bfloat16* __restrict__ Wl,
    const float* __restrict__ bias,
    float* __restrict__ C, int ldc, int M,
    __nv_bfloat16* __restrict__ Dh, __nv_bfloat16* __restrict__ Dl,
    int mode,
    const float* __restrict__ b1, const float* __restrict__ b2,
    const float* __restrict__ b3)
{
    extern __shared__ char smem[];
    uint32_t sb = cvta_s(smem);
    const int tid  = threadIdx.x;
    const int wid  = tid >> 5;
    const int lane = tid & 31;
    const int wm   = wid >> 1;
    const int wn   = wid & 1;
    const int mbase = blockIdx.x * 128;
    const int nbase = blockIdx.y * 128;
    const int Kt = K0 + K1;
    const int nk = Kt >> 5;

    float* bs1 = (float*)(smem + SM_BIAS);
    float* bs2 = bs1 + 128;
    float* bs3 = bs2 + 128;
    if (tid < 128) {
        if (mode == 2) {
            bs1[tid] = b1[tid]; bs2[tid] = b2[tid]; bs3[tid] = b3[tid];
        } else {
            bs1[tid] = bias ? bias[nbase + tid] : 0.f;
        }
    }

    // ldmatrix lane geometry (swizzled 64B rows)
    const int hi = lane >> 4;                 // A col-half select
    const int jj = lane >> 3;                 // B quadrant select
    const int a_row0 = wm * 32 + (lane & 15); // rows for mt=0 (mt*16 keeps xr)
    const uint32_t xr_a = (uint32_t)((a_row0 >> 1) & 3);
    const uint32_t a_ro[2] = {(uint32_t)(a_row0 * 64), (uint32_t)((a_row0 + 16) * 64)};
    const int b_row0 = wn * 64 + ((jj >> 1) * 8) + (lane & 7);
    const uint32_t xr_b = (uint32_t)((b_row0 >> 1) & 3);
    const uint32_t b_ro = (uint32_t)(b_row0 * 64);
    const uint32_t b_ch = (uint32_t)(jj & 1);

    float acc[2][8][4];
    #pragma unroll
    for (int mt = 0; mt < 2; mt++)
        #pragma unroll
        for (int nt = 0; nt < 8; nt++)
            #pragma unroll
            for (int j = 0; j < 4; j++) acc[mt][nt][j] = 0.f;

    issue_tile(sb, 0, 0, A0h, A0l, K0, A1h, A1l, K1, Wh, Wl, Kt, mbase, nbase, tid);
    CPCOMMIT();
    if (nk > 1)
        issue_tile(sb, 1, 1, A0h, A0l, K0, A1h, A1l, K1, Wh, Wl, Kt, mbase, nbase, tid);
    CPCOMMIT();

    for (int kt = 0; kt < nk; kt++) {
        int stage = kt % 3;
        CPWAIT1();
        __syncthreads();
        uint32_t base = sb + stage * STAGE_B;
        #pragma unroll
        for (int s = 0; s < 2; s++) {
            uint32_t ca = ((uint32_t)(s * 2 + hi) ^ xr_a) * 16;
            uint32_t cb = ((uint32_t)(s * 2) + b_ch ^ xr_b) * 16;
            uint32_t ah[2][4], al[2][4];
            #pragma unroll
            for (int mt = 0; mt < 2; mt++) {
                uint32_t ad = base + a_ro[mt] + ca;
                LDSM4(ah[mt][0], ah[mt][1], ah[mt][2], ah[mt][3], ad);
                LDSM4(al[mt][0], al[mt][1], al[mt][2], al[mt][3], ad + TILE_B);
            }
            uint32_t bh[8][2], bl[8][2];
            #pragma unroll
            for (int g = 0; g < 4; g++) {
                uint32_t bd = base + 2 * TILE_B + b_ro + g * 1024 + cb;
                uint32_t r0, r1, r2, r3;
                LDSM4(r0, r1, r2, r3, bd);
                bh[g * 2][0] = r0; bh[g * 2][1] = r1;
                bh[g * 2 + 1][0] = r2; bh[g * 2 + 1][1] = r3;
                LDSM4(r0, r1, r2, r3, bd + TILE_B);
                bl[g * 2][0] = r0; bl[g * 2][1] = r1;
                bl[g * 2 + 1][0] = r2; bl[g * 2 + 1][1] = r3;
            }
            #pragma unroll
            for (int mt = 0; mt < 2; mt++)
                #pragma unroll
                for (int nt = 0; nt < 8; nt++) {
                    MMA16816(acc[mt][nt], ah[mt], bh[nt][0], bh[nt][1]);
                    MMA16816(acc[mt][nt], ah[mt], bl[nt][0], bl[nt][1]);
                    MMA16816(acc[mt][nt], al[mt], bh[nt][0], bh[nt][1]);
                }
        }
        if (kt + 2 < nk)
            issue_tile(sb, (kt + 2) % 3, kt + 2, A0h, A0l, K0, A1h, A1l, K1,
                       Wh, Wl, Kt, mbase, nbase, tid);
        CPCOMMIT();
    }

    // ---- epilogue ----
    #pragma unroll
    for (int mt = 0; mt < 2; mt++) {
        int r0 = mbase + wm * 32 + mt * 16 + (lane >> 2);
        int r1 = r0 + 8;
        float ci0 = 0.f, cb0 = 0.f, cc0 = 0.f, inv0 = 1.f;
        float ci1 = 0.f, cb1 = 0.f, cc1 = 0.f, inv1 = 1.f;
        if (mode == 2) {
            if (r0 < N_INTn) {
                ci0 = g_cntI[r0]; cb0 = g_cntB[r0]; cc0 = g_cntC[r0];
                inv0 = 1.f / fmaxf(ci0 + cb0 + cc0, 1.f);
            }
            if (r1 < N_INTn) {
                ci1 = g_cntI[r1]; cb1 = g_cntB[r1]; cc1 = g_cntC[r1];
                inv1 = 1.f / fmaxf(ci1 + cb1 + cc1, 1.f);
            }
        }
        #pragma unroll
        for (int nt = 0; nt < 8; nt++) {
            int nl = wn * 64 + nt * 8 + (lane & 3) * 2;
            float v00 = acc[mt][nt][0], v01 = acc[mt][nt][1];
            float v10 = acc[mt][nt][2], v11 = acc[mt][nt][3];
            if (mode == 0) {
                float b0 = bs1[nl], b1v = bs1[nl + 1];
                if (r0 < M) {
                    float2 o = {v00 + b0, v01 + b1v};
                    *reinterpret_cast<float2*>(C + (size_t)r0 * ldc + nbase + nl) = o;
                }
                if (r1 < M) {
                    float2 o = {v10 + b0, v11 + b1v};
                    *reinterpret_cast<float2*>(C + (size_t)r1 * ldc + nbase + nl) = o;
                }
            } else if (mode == 1) {
                float b0 = bs1[nl], b1v = bs1[nl + 1];
                v00 += b0; v01 += b1v; v10 += b0; v11 += b1v;
                size_t i0 = (size_t)r0 * 128 + nbase + nl;
                size_t i1 = (size_t)r1 * 128 + nbase + nl;
                *reinterpret_cast<uint32_t*>(Dh + i0) = pack_bf2(v00, v01);
                *reinterpret_cast<uint32_t*>(Dl + i0) = pack_lo2(v00, v01);
                *reinterpret_cast<uint32_t*>(Dh + i1) = pack_bf2(v10, v11);
                *reinterpret_cast<uint32_t*>(Dl + i1) = pack_lo2(v10, v11);
            } else {
                float e0 = bs1[nl] , e1 = bs1[nl + 1];
                float f0 = bs2[nl] , f1 = bs2[nl + 1];
                float g0 = bs3[nl] , g1 = bs3[nl + 1];
                v00 = (v00 + ci0 * e0 + cb0 * f0 + cc0 * g0) * inv0;
                v01 = (v01 + ci0 * e1 + cb0 * f1 + cc0 * g1) * inv0;
                v10 = (v10 + ci1 * e0 + cb1 * f0 + cc1 * g0) * inv1;
                v11 = (v11 + ci1 * e1 + cb1 * f1 + cc1 * g1) * inv1;
                size_t i0 = (size_t)r0 * 128 + nbase + nl;
                size_t i1 = (size_t)r1 * 128 + nbase + nl;
                *reinterpret_cast<uint32_t*>(Dh + i0) = pack_bf2(v00, v01);
                *reinterpret_cast<uint32_t*>(Dl + i0) = pack_lo2(v00, v01);
                *reinterpret_cast<uint32_t*>(Dh + i1) = pack_bf2(v10, v11);
                *reinterpret_cast<uint32_t*>(Dl + i1) = pack_lo2(v10, v11);
            }
        }
    }
}

// ---------------- zero scratch ----------------
__global__ void k_zero() {
    int idx = blockIdx.x * blockDim.x + threadIdx.x;
    int stride = gridDim.x * blockDim.x;
    float4 z = {0.f, 0.f, 0.f, 0.f};
    float4* f = reinterpret_cast<float4*>(g_feat);
    for (int i = idx; i < N_INTn * 320 / 4; i += stride) f[i] = z;
    for (int i = idx; i < N_INTn; i += stride) {
        g_cntI[i] = 0.f; g_cntB[i] = 0.f; g_cntC[i] = 0.f;
    }
}

// ---------------- fused edge scatter ----------------
__device__ __forceinline__ void red4(float* p, float4 v) {
    asm volatile("red.global.add.v4.f32 [%0], {%1,%2,%3,%4};"
                 :: "l"(p), "f"(v.x), "f"(v.y), "f"(v.z), "f"(v.w) : "memory");
}

constexpr int W_INT = E_INTn / 4;               // 125000
constexpr int W_B   = W_INT + E_Bn / 4;         // 130000
constexpr int W_C   = W_B + E_Cn / 4;           // 132500

__global__ void k_scatter(const int* __restrict__ eiI, const int* __restrict__ eiB,
                          const int* __restrict__ eiC,
                          const float* __restrict__ x, const float* __restrict__ xb,
                          const float* __restrict__ u)
{
    int w = (blockIdx.x * blockDim.x + threadIdx.x) >> 5;
    int lane = threadIdx.x & 31;
    if (w < W_INT) {
        int e0 = w * 4;
        int s[4], t[4];
        #pragma unroll
        for (int j = 0; j < 4; j++) { s[j] = eiI[e0 + j]; t[j] = eiI[E_INTn + e0 + j]; }
        float4 v[4];
        #pragma unroll
        for (int j = 0; j < 4; j++)
            v[j] = ((const float4*)(x + (size_t)s[j] * D))[lane];
        #pragma unroll
        for (int j = 0; j < 4; j++)
            red4(g_feat + (size_t)t[j] * 320 + lane * 4, v[j]);
        if (lane == 0) {
            #pragma unroll
            for (int j = 0; j < 4; j++) atomicAdd(&g_cntI[t[j]], 1.0f);
        }
    } else if (w < W_B) {
        int e0 = (w - W_INT) * 4;
        int t[4];
        #pragma unroll
        for (int j = 0; j < 4; j++) t[j] = eiB[E_Bn + e0 + j];
        float4 v[4];
        #pragma unroll
        for (int j = 0; j < 4; j++)
            v[j] = ((const float4*)(xb + (size_t)(e0 + j) * D))[lane];
        #pragma unroll
        for (int j = 0; j < 4; j++)
            red4(g_feat + (size_t)t[j] * 320 + 128 + lane * 4, v[j]);
        if (lane == 0) {
            #pragma unroll
            for (int j = 0; j < 4; j++) atomicAdd(&g_cntB[t[j]], 1.0f);
        }
    } else if (w < W_C) {
        int e0 = (w - W_B) * 4;
        int t[4];
        #pragma unroll
        for (int j = 0; j < 4; j++) t[j] = eiC[E_Cn + e0 + j];
        if (lane < 16) {
            float4 v[4];
            #pragma unroll
            for (int j = 0; j < 4; j++)
                v[j] = ((const float4*)(u + (size_t)(e0 + j) * DCn))[lane];
            #pragma unroll
            for (int j = 0; j < 4; j++)
                red4(g_feat + (size_t)t[j] * 320 + 256 + lane * 4, v[j]);
        }
        if (lane == 0) {
            #pragma unroll
            for (int j = 0; j < 4; j++) atomicAdd(&g_cntC[t[j]], 1.0f);
        }
    }
}

// ---------------- prep helpers ----------------
__device__ __forceinline__ void wsplit(float v, __nv_bfloat16* h, __nv_bfloat16* l, size_t i) {
    __nv_bfloat16 hi = __float2bfloat16_rn(v);
    h[i] = hi;
    l[i] = __float2bfloat16_rn(v - __bfloat162float(hi));
}

// ---- prep_rest: weights + biases + x/xb/u planes (independent of scatter) ----
constexpr int R_W1  = 128 * KFE;            // 90112
constexpr int R_WOI = R_W1 + 65536;
constexpr int R_WB1 = R_WOI + 16384;
constexpr int R_WOB = R_WB1 + 65536;
constexpr int R_WC1 = R_WOB + 8192;
constexpr int R_WOC = R_WC1 + 49152;
constexpr int R_B1  = R_WOC + 256;
constexpr int R_B2  = R_B1 + 256;
constexpr int R_B3  = R_B2 + 256;          // 295680
constexpr int R_X   = R_B3 + NP_I * 128;
constexpr int R_XB  = R_X + NP_B * 128;
constexpr int R_U   = R_XB + NP_C * 64;    // total ~9.92M

__global__ void k_prep_rest(
    const float* __restrict__ x, const float* __restrict__ xb, const float* __restrict__ u,
    const float* __restrict__ Wii, const float* __restrict__ Wbi, const float* __restrict__ Wci,
    const float* __restrict__ Wbb, const float* __restrict__ Wcc,
    const float* __restrict__ Wis, const float* __restrict__ Wim,
    const float* __restrict__ Wbs, const float* __restrict__ Wbm,
    const float* __restrict__ Wcs, const float* __restrict__ Wcm,
    const float* __restrict__ bis, const float* __restrict__ bim,
    const float* __restrict__ bbs, const float* __restrict__ bbm,
    const float* __restrict__ bcs, const float* __restrict__ bcm)
{
    int idx = blockIdx.x * blockDim.x + threadIdx.x;
    if (idx < R_W1) {
        int i = idx;
        int j = i / KFE, k = i % KFE;
        float v;
        if (k < 128)      v = Wii[j * 256 + k];
        else if (k < 256) v = Wbi[j * 256 + (k - 128)];
        else if (k < 320) v = Wci[j * 192 + (k - 256)];
        else if (k < 448) v = Wii[j * 256 + 128 + (k - 320)];
        else if (k < 576) v = Wbi[j * 256 + 128 + (k - 448)];
        else              v = Wci[j * 192 + 64 + (k - 576)];
        wsplit(v, g_W1h, g_W1l, i);
        return;
    }
    if (idx < R_WOI) {
        int i = idx - R_W1;
        int j = i / 256, k = i % 256;
        float v = (k < 128) ? Wis[j * 128 + k] : Wim[j * 128 + (k - 128)];
        wsplit(v, g_WOIh, g_WOIl, i);
        return;
    }
    if (idx < R_WB1) {
        int i = idx - R_WOI;
        int j = i / 128, k = i % 128;
        wsplit(Wbb[j * 256 + k] + Wbb[j * 256 + 128 + k], g_WB1h, g_WB1l, i);
        return;
    }
    if (idx < R_WOB) {
        int i = idx - R_WB1;
        int j = i / 256, k = i % 256;
        float v = (k < 128) ? Wbs[j * 128 + k] : Wbm[j * 128 + (k - 128)];
        wsplit(v, g_WOBh, g_WOBl, i);
        return;
    }
    if (idx < R_WC1) {
        int i = idx - R_WOB;
        int j = i / 64, k = i % 64;
        wsplit(Wcc[j * 128 + k] + Wcc[j * 128 + 64 + k], g_WC1h, g_WC1l, i);
        return;
    }
    if (idx < R_WOC) {
        int i = idx - R_WC1;
        int j = i / 192, k = i % 192;
        float v = (k < 64) ? Wcs[j * 64 + k] : Wcm[j * 128 + (k - 64)];
        wsplit(v, g_WOCh, g_WOCl, i);
        return;
    }
    if (idx < R_B1) { int i = idx - R_WOC; g_bOI[i] = bis[i] + bim[i]; return; }
    if (idx < R_B2) { int i = idx - R_B1;  g_bOB[i] = bbs[i] + bbm[i]; return; }
    if (idx < R_B3) { int i = idx - R_B2;  g_bOC[i] = bcs[i] + bcm[i]; return; }
    if (idx < R_X) {
        int i = idx - R_B3;
        int m = i >> 7, k = i & 127;
        float v = (m < N_INTn) ? x[(size_t)m * 128 + k] : 0.f;
        wsplit(v, g_xh, g_xl, (size_t)i);
        return;
    }
    if (idx < R_XB) {
        int i = idx - R_X;
        int m = i >> 7, k = i & 127;
        float v = (m < E_Bn) ? xb[(size_t)m * 128 + k] : 0.f;
        wsplit(v, g_xbh, g_xbl, (size_t)i);
        return;
    }
    if (idx < R_U) {
        int i = idx - R_XB;
        int m = i >> 6, k = i & 63;
        float v = (m < E_Cn) ? u[(size_t)m * 64 + k] : 0.f;
        wsplit(v, g_uh, g_ul, (size_t)i);
        return;
    }
}

// ---- prep_feat: featext planes (needs scatter results) ----
constexpr long long F_FEAT = (long long)NP_I * 320;
constexpr long long F_TOT  = F_FEAT + (long long)NP_I * 128;

__global__ void k_prep_feat(const float* __restrict__ x)
{
    long long idx = (long long)blockIdx.x * blockDim.x + threadIdx.x;
    if (idx < F_FEAT) {
        int m = (int)(idx / 320), k = (int)(idx % 320);
        float v = (m < N_INTn) ? g_feat[(size_t)m * 320 + k] : 0.f;
        wsplit(v, g_feh, g_fel, (size_t)m * KFE + k);
        return;
    }
    if (idx < F_TOT) {
        long long i = idx - F_FEAT;
        int m = (int)(i >> 7), k = (int)(i & 127);
        float xv = 0.f, ci = 0.f, cb = 0.f, cc = 0.f;
        if (m < N_INTn) {
            xv = x[(size_t)m * 128 + k];
            ci = g_cntI[m]; cb = g_cntB[m]; cc = g_cntC[m];
        }
        size_t base = (size_t)m * KFE;
        wsplit(ci * xv, g_feh, g_fel, base + 320 + k);
        wsplit(cb * xv, g_feh, g_fel, base + 448 + k);
        wsplit(cc * xv, g_feh, g_fel, base + 576 + k);
        return;
    }
}

// ---------------- launch ----------------
static void* symv(const void* s) { void* p = nullptr; cudaGetSymbolAddress(&p, s); return p; }

extern "C" void kernel_launch(void* const* d_in, const int* in_sizes, int n_in,
                              void* d_out, int out_size) {
    const float* x   = (const float*)d_in[0];
    const float* xb  = (const float*)d_in[1];
    const float* u   = (const float*)d_in[2];
    const int*   eiI = (const int*)d_in[3];
    const int*   eiB = (const int*)d_in[4];
    const int*   eiC = (const int*)d_in[5];
    const float* Wii = (const float*)d_in[8];
    const float* bii = (const float*)d_in[9];
    const float* Wbi = (const float*)d_in[10];
    const float* bbi = (const float*)d_in[11];
    const float* Wci = (const float*)d_in[12];
    const float* bci = (const float*)d_in[13];
    const float* Wbb = (const float*)d_in[14];
    const float* bbb = (const float*)d_in[15];
    const float* Wcc = (const float*)d_in[16];
    const float* bcc = (const float*)d_in[17];
    const float* Wim = (const float*)d_in[18];
    const float* bim = (const float*)d_in[19];
    const float* Wis = (const float*)d_in[20];
    const float* bis = (const float*)d_in[21];
    const float* Wbm = (const float*)d_in[22];
    const float* bbm = (const float*)d_in[23];
    const float* Wbs = (const float*)d_in[24];
    const float* bbs = (const float*)d_in[25];
    const float* Wcm = (const float*)d_in[26];
    const float* bcm = (const float*)d_in[27];
    const float* Wcs = (const float*)d_in[28];
    const float* bcs = (const float*)d_in[29];
    float* out = (float*)d_out;

    auto bfp = [](const void* s) { return (const __nv_bfloat16*)symv(s); };
    auto bfw = [](const void* s) { return (__nv_bfloat16*)symv(s); };

    const __nv_bfloat16 *pxh = bfp(g_xh), *pxl = bfp(g_xl);
    const __nv_bfloat16 *pxbh = bfp(g_xbh), *pxbl = bfp(g_xbl);
    const __nv_bfloat16 *puh = bfp(g_uh), *pul = bfp(g_ul);
    const __nv_bfloat16 *pfeh = bfp(g_feh), *pfel = bfp(g_fel);
    __nv_bfloat16 *paggh = bfw(g_aggh), *paggl = bfw(g_aggl);
    __nv_bfloat16 *psbh = bfw(g_sbh), *psbl = bfw(g_sbl);
    __nv_bfloat16 *psch = bfw(g_sch), *pscl = bfw(g_scl);
    const __nv_bfloat16 *pW1h = bfp(g_W1h), *pW1l = bfp(g_W1l);
    const __nv_bfloat16 *pWOIh = bfp(g_WOIh), *pWOIl = bfp(g_WOIl);
    const __nv_bfloat16 *pWB1h = bfp(g_WB1h), *pWB1l = bfp(g_WB1l);
    const __nv_bfloat16 *pWOBh = bfp(g_WOBh), *pWOBl = bfp(g_WOBl);
    const __nv_bfloat16 *pWC1h = bfp(g_WC1h), *pWC1l = bfp(g_WC1l);
    const __nv_bfloat16 *pWOCh = bfp(g_WOCh), *pWOCl = bfp(g_WOCl);
    const float *pbOI = (const float*)symv(g_bOI);
    const float *pbOB = (const float*)symv(g_bOB);
    const float *pbOC = (const float*)symv(g_bOC);

    // streams/events: created once, on the first (non-captured) call
    static cudaStream_t s1 = nullptr;
    static cudaEvent_t evF = nullptr, evR = nullptr, evJ = nullptr;
    if (s1 == nullptr) {
        cudaStreamCreateWithFlags(&s1, cudaStreamNonBlocking);
        cudaEventCreateWithFlags(&evF, cudaEventDisableTiming);
        cudaEventCreateWithFlags(&evR, cudaEventDisableTiming);
        cudaEventCreateWithFlags(&evJ, cudaEventDisableTiming);
        cudaFuncSetAttribute(k_gemm, cudaFuncAttributeMaxDynamicSharedMemorySize, SM_TOT);
    }

    // fork: s1 runs prep_rest + boundary/control chain
    cudaEventRecord(evF, 0);
    cudaStreamWaitEvent(s1, evF, 0);

    k_prep_rest<<<(R_U + 255) / 256, 256, 0, s1>>>(
        x, xb, u, Wii, Wbi, Wci, Wbb, Wcc, Wis, Wim, Wbs, Wbm, Wcs, Wcm,
        bis, bim, bbs, bbm, bcs, bcm);
    cudaEventRecord(evR, s1);
    // SB = xb @ WB1^T + bbb -> planes
    k_gemm<<<dim3(157, 1), 256, SM_TOT, s1>>>(
        pxbh, pxbl, 128, nullptr, nullptr, 0, pWB1h, pWB1l,
        bbb, nullptr, 0, 0, psbh, psbl, 1, nullptr, nullptr, nullptr);
    // OUT-B = [xb | SB] @ WOB^T + bOB
    k_gemm<<<dim3(157, 2), 256, SM_TOT, s1>>>(
        pxbh, pxbl, 128, psbh, psbl, 128, pWOBh, pWOBl,
        pbOB, out + (size_t)N_INTn * 256, 256, E_Bn, nullptr, nullptr, 0,
        nullptr, nullptr, nullptr);
    // SC = u @ WC1^T + bcc -> planes
    k_gemm<<<dim3(79, 1), 256, SM_TOT, s1>>>(
        puh, pul, 64, nullptr, nullptr, 0, pWC1h, pWC1l,
        bcc, nullptr, 0, 0, psch, pscl, 1, nullptr, nullptr, nullptr);
    // OUT-C = [u | SC] @ WOC^T + bOC
    k_gemm<<<dim3(79, 2), 256, SM_TOT, s1>>>(
        puh, pul, 64, psch, pscl, 128, pWOCh, pWOCl,
        pbOC, out + (size_t)(N_INTn + E_Bn) * 256, 256, E_Cn, nullptr, nullptr, 0,
        nullptr, nullptr, nullptr);
    cudaEventRecord(evJ, s1);

    // s0 (default): zero -> scatter -> prep_feat -> interior GEMMs
    k_zero<<<1024, 256>>>();
    k_scatter<<<(W_C * 32 + 255) / 256, 256>>>(eiI, eiB, eiC, x, xb, u);
    k_prep_feat<<<(int)((F_TOT + 255) / 256), 256>>>(x);

    cudaStreamWaitEvent(0, evR, 0);   // need W1 planes + x planes for interior chain
    // AGG = featext @ W1ext^T, epilogue: (+ci*bii+cb*bbi+cc*bci)/cnt -> planes
    k_gemm<<<dim3(391, 1), 256, SM_TOT>>>(
        pfeh, pfel, KFE, nullptr, nullptr, 0, pW1h, pW1l,
        nullptr, nullptr, 0, 0, paggh, paggl, 2, bii, bbi, bci);
    // OUT-I = [x | AGG] @ WOI^T + bOI
    k_gemm<<<dim3(391, 2), 256, SM_TOT>>>(
        pxh, pxl, 128, paggh, paggl, 128, pWOIh, pWOIl,
        pbOI, out, 256, N_INTn, nullptr, nullptr, 0, nullptr, nullptr, nullptr);

    // join
    cudaStreamWaitEvent(0, evJ, 0);
}